// round 1
// baseline (speedup 1.0000x reference)
#include <cuda_runtime.h>
#include <math.h>

#define EMBED   768
#define HEADS   12
#define HDIM    64
#define HIDDEN  3072
#define BATCHSZ 8
#define SEQ     1024
#define TOKENS  (BATCHSZ*SEQ)     // 8192
#define BHT     (BATCHSZ*HEADS)   // 96

// ---------------- scratch (static device globals; no cudaMalloc allowed) ----
__device__ float g_h   [(size_t)TOKENS*EMBED];        // LN1 out
__device__ float g_qkv [(size_t)TOKENS*3*EMBED];      // packed qkv [tok, 3*768]
__device__ float g_S   [(size_t)BHT*SEQ*SEQ];         // attention scores/probs
__device__ float g_attn[(size_t)TOKENS*EMBED];        // attn output (pre-proj)
__device__ float g_x2  [(size_t)TOKENS*EMBED];        // residual after proj
__device__ float g_h2  [(size_t)TOKENS*EMBED];        // LN2 out
__device__ float g_hid [(size_t)TOKENS*HIDDEN];       // FC1+GELU out

// ---------------- LayerNorm: one block per row of 768 -----------------------
__global__ void ln_kernel(const float* __restrict__ x,
                          const float* __restrict__ g,
                          const float* __restrict__ b,
                          float* __restrict__ out) {
    int row = blockIdx.x;
    const float* xr = x + (size_t)row * EMBED;
    float s = 0.f, s2 = 0.f;
    for (int i = threadIdx.x; i < EMBED; i += blockDim.x) {
        float v = xr[i]; s += v; s2 += v * v;
    }
    __shared__ float red[64];
    int wid = threadIdx.x >> 5, lid = threadIdx.x & 31;
    #pragma unroll
    for (int o = 16; o; o >>= 1) {
        s  += __shfl_down_sync(0xffffffffu, s,  o);
        s2 += __shfl_down_sync(0xffffffffu, s2, o);
    }
    if (lid == 0) { red[wid] = s; red[wid + 32] = s2; }
    __syncthreads();
    if (wid == 0) {
        int nw = blockDim.x >> 5;
        s  = (lid < nw) ? red[lid]      : 0.f;
        s2 = (lid < nw) ? red[lid + 32] : 0.f;
        #pragma unroll
        for (int o = 16; o; o >>= 1) {
            s  += __shfl_down_sync(0xffffffffu, s,  o);
            s2 += __shfl_down_sync(0xffffffffu, s2, o);
        }
        if (lid == 0) { red[0] = s; red[1] = s2; }
    }
    __syncthreads();
    float mu  = red[0] * (1.f / EMBED);
    float var = red[1] * (1.f / EMBED) - mu * mu;
    float rstd = rsqrtf(var + 1e-5f);
    float* o = out + (size_t)row * EMBED;
    for (int i = threadIdx.x; i < EMBED; i += blockDim.x)
        o[i] = (xr[i] - mu) * rstd * g[i] + b[i];
}

// ---------------- row softmax over SEQ=1024: one block per row ---------------
__global__ void softmax_kernel(float* __restrict__ S) {
    size_t row = blockIdx.x;
    float* r = S + row * SEQ;
    int wid = threadIdx.x >> 5, lid = threadIdx.x & 31;
    int nw = blockDim.x >> 5;
    __shared__ float red[32];

    float m = -1e30f;
    for (int i = threadIdx.x; i < SEQ; i += blockDim.x) m = fmaxf(m, r[i]);
    #pragma unroll
    for (int o = 16; o; o >>= 1) m = fmaxf(m, __shfl_xor_sync(0xffffffffu, m, o));
    if (lid == 0) red[wid] = m;
    __syncthreads();
    if (threadIdx.x < 32) {
        float t = (lid < nw) ? red[lid] : -1e30f;
        #pragma unroll
        for (int o = 16; o; o >>= 1) t = fmaxf(t, __shfl_xor_sync(0xffffffffu, t, o));
        if (lid == 0) red[0] = t;
    }
    __syncthreads();
    m = red[0];
    __syncthreads();   // everyone has read red[0] before it is reused

    float s = 0.f;
    for (int i = threadIdx.x; i < SEQ; i += blockDim.x) {
        float e = __expf(r[i] - m);
        r[i] = e;
        s += e;
    }
    #pragma unroll
    for (int o = 16; o; o >>= 1) s += __shfl_xor_sync(0xffffffffu, s, o);
    if (lid == 0) red[wid] = s;
    __syncthreads();
    if (threadIdx.x < 32) {
        float t = (lid < nw) ? red[lid] : 0.f;
        #pragma unroll
        for (int o = 16; o; o >>= 1) t += __shfl_xor_sync(0xffffffffu, t, o);
        if (lid == 0) red[0] = t;
    }
    __syncthreads();
    float inv = 1.f / red[0];
    for (int i = threadIdx.x; i < SEQ; i += blockDim.x) r[i] *= inv;
}

// ---------------- generic tiled SGEMM -----------------------------------------
// C = alpha * A(MxK) * op(B) (+bias[col]) (+GELU) (+res), op(B)=B or B^T.
// Batched via blockIdx.z with (z/HB, z%HB) stride decomposition.
// All dims must be multiples of the tile sizes (true for every call here).
template<int BM, int BN, int BK, int TM, int TN, bool TRANSB, bool GELU>
__global__ void __launch_bounds__((BM/TM)*(BN/TN))
gemm_kernel(const float* __restrict__ A, const float* __restrict__ B,
            float* __restrict__ C,
            int M, int N, int K, int lda, int ldb, int ldc,
            long long sA1, long long sA2,
            long long sB1, long long sB2,
            long long sC1, long long sC2, int HB,
            float alpha,
            const float* __restrict__ bias,
            const float* __restrict__ res) {
    constexpr int NT = (BM / TM) * (BN / TN);
    const int tid = threadIdx.x;
    const int z = blockIdx.z;
    const int zb = z / HB, zh = z % HB;
    A += (size_t)zb * sA1 + (size_t)zh * sA2;
    B += (size_t)zb * sB1 + (size_t)zh * sB2;
    C += (size_t)zb * sC1 + (size_t)zh * sC2;
    if (res) res += (size_t)zb * sC1 + (size_t)zh * sC2;

    const int m0 = blockIdx.y * BM;
    const int n0 = blockIdx.x * BN;
    const int tcol = tid % (BN / TN);
    const int trow = tid / (BN / TN);

    __shared__ float As[BK][BM + 4];
    __shared__ float Bs[BK][BN + 4];

    float acc[TM][TN];
    #pragma unroll
    for (int i = 0; i < TM; i++)
        #pragma unroll
        for (int j = 0; j < TN; j++) acc[i][j] = 0.f;

    for (int k0 = 0; k0 < K; k0 += BK) {
        #pragma unroll
        for (int i = tid; i < BM * BK; i += NT) {
            int m = i / BK, k = i % BK;
            As[k][m] = A[(size_t)(m0 + m) * lda + (k0 + k)];
        }
        if (!TRANSB) {
            #pragma unroll
            for (int i = tid; i < BK * BN; i += NT) {
                int k = i / BN, n = i % BN;
                Bs[k][n] = B[(size_t)(k0 + k) * ldb + (n0 + n)];
            }
        } else {
            #pragma unroll
            for (int i = tid; i < BN * BK; i += NT) {
                int n = i / BK, k = i % BK;
                Bs[k][n] = B[(size_t)(n0 + n) * ldb + (k0 + k)];
            }
        }
        __syncthreads();

        #pragma unroll
        for (int k = 0; k < BK; k++) {
            float ra[TM], rb[TN];
            #pragma unroll
            for (int i = 0; i < TM; i++) ra[i] = As[k][trow * TM + i];
            #pragma unroll
            for (int j = 0; j < TN; j++) rb[j] = Bs[k][tcol * TN + j];
            #pragma unroll
            for (int i = 0; i < TM; i++)
                #pragma unroll
                for (int j = 0; j < TN; j++)
                    acc[i][j] += ra[i] * rb[j];
        }
        __syncthreads();
    }

    #pragma unroll
    for (int i = 0; i < TM; i++) {
        int m = m0 + trow * TM + i;
        #pragma unroll
        for (int j = 0; j < TN; j++) {
            int n = n0 + tcol * TN + j;
            float v = acc[i][j] * alpha;
            if (bias) v += bias[n];
            if (GELU) v = 0.5f * v * (1.f + erff(v * 0.70710678118654752f));
            if (res)  v += res[(size_t)m * ldc + n];
            C[(size_t)m * ldc + n] = v;
        }
    }
}

// ---------------- launch --------------------------------------------------------
extern "C" void kernel_launch(void* const* d_in, const int* in_sizes, int n_in,
                              void* d_out, int out_size) {
    const float* x      = (const float*)d_in[0];
    const float* g1     = (const float*)d_in[1];
    const float* b1     = (const float*)d_in[2];
    const float* g2     = (const float*)d_in[3];
    const float* b2     = (const float*)d_in[4];
    const float* w_qkv  = (const float*)d_in[5];
    const float* w_proj = (const float*)d_in[6];
    const float* b_proj = (const float*)d_in[7];
    const float* w_fc1  = (const float*)d_in[8];
    const float* b_fc1  = (const float*)d_in[9];
    const float* w_fc2  = (const float*)d_in[10];
    const float* b_fc2  = (const float*)d_in[11];
    float* out = (float*)d_out;

    float *p_h, *p_qkv, *p_S, *p_attn, *p_x2, *p_h2, *p_hid;
    cudaGetSymbolAddress((void**)&p_h,    g_h);
    cudaGetSymbolAddress((void**)&p_qkv,  g_qkv);
    cudaGetSymbolAddress((void**)&p_S,    g_S);
    cudaGetSymbolAddress((void**)&p_attn, g_attn);
    cudaGetSymbolAddress((void**)&p_x2,   g_x2);
    cudaGetSymbolAddress((void**)&p_h2,   g_h2);
    cudaGetSymbolAddress((void**)&p_hid,  g_hid);

    const long long ZL = 0;

    // 1) LN1
    ln_kernel<<<TOKENS, 256>>>(x, g1, b1, p_h);

    // 2) qkv = h @ w_qkv   (8192 x 2304 x 768)
    gemm_kernel<128,128,8,8,8,false,false>
        <<<dim3(3*EMBED/128, TOKENS/128, 1), 256>>>(
        p_h, w_qkv, p_qkv,
        TOKENS, 3*EMBED, EMBED, EMBED, 3*EMBED, 3*EMBED,
        ZL, ZL, ZL, ZL, ZL, ZL, 1, 1.f, nullptr, nullptr);

    // 3) S = Q @ K^T * scale   (96 batches of 1024x1024x64)
    gemm_kernel<128,128,8,8,8,true,false>
        <<<dim3(SEQ/128, SEQ/128, BHT), 256>>>(
        p_qkv /*Q*/, p_qkv + EMBED /*K*/, p_S,
        SEQ, SEQ, HDIM, 3*EMBED, 3*EMBED, SEQ,
        (long long)SEQ*3*EMBED, (long long)HDIM,          // Q strides (b,h)
        (long long)SEQ*3*EMBED, (long long)HDIM,          // K strides (b,h)
        (long long)HEADS*SEQ*SEQ, (long long)SEQ*SEQ,     // S strides (b,h)
        HEADS, 0.125f, nullptr, nullptr);

    // 4) softmax rows
    softmax_kernel<<<BHT*SEQ, 256>>>(p_S);

    // 5) O = P @ V   (96 batches of 1024x64x1024)
    gemm_kernel<128,64,8,8,4,false,false>
        <<<dim3(HDIM/64, SEQ/128, BHT), 256>>>(
        p_S, p_qkv + 2*EMBED /*V*/, p_attn,
        SEQ, HDIM, SEQ, SEQ, 3*EMBED, EMBED,
        (long long)HEADS*SEQ*SEQ, (long long)SEQ*SEQ,     // P strides
        (long long)SEQ*3*EMBED, (long long)HDIM,          // V strides
        (long long)SEQ*EMBED, (long long)HDIM,            // O strides
        HEADS, 1.f, nullptr, nullptr);

    // 6) x2 = attn @ w_proj + b_proj + x
    gemm_kernel<128,128,8,8,8,false,false>
        <<<dim3(EMBED/128, TOKENS/128, 1), 256>>>(
        p_attn, w_proj, p_x2,
        TOKENS, EMBED, EMBED, EMBED, EMBED, EMBED,
        ZL, ZL, ZL, ZL, ZL, ZL, 1, 1.f, b_proj, x);

    // 7) LN2
    ln_kernel<<<TOKENS, 256>>>(p_x2, g2, b2, p_h2);

    // 8) hid = gelu(h2 @ w_fc1 + b_fc1)
    gemm_kernel<128,128,8,8,8,false,true>
        <<<dim3(HIDDEN/128, TOKENS/128, 1), 256>>>(
        p_h2, w_fc1, p_hid,
        TOKENS, HIDDEN, EMBED, EMBED, HIDDEN, HIDDEN,
        ZL, ZL, ZL, ZL, ZL, ZL, 1, 1.f, b_fc1, nullptr);

    // 9) out = hid @ w_fc2 + b_fc2 + x2
    gemm_kernel<128,128,8,8,8,false,false>
        <<<dim3(EMBED/128, TOKENS/128, 1), 256>>>(
        p_hid, w_fc2, out,
        TOKENS, EMBED, HIDDEN, HIDDEN, EMBED, EMBED,
        ZL, ZL, ZL, ZL, ZL, ZL, 1, 1.f, b_fc2, p_x2);
}

// round 2
// speedup vs baseline: 2.7189x; 2.7189x over previous
#include <cuda_runtime.h>
#include <math.h>
#include <stdint.h>

#define EMBED   768
#define HEADS   12
#define HDIM    64
#define HIDDEN  3072
#define BATCHSZ 8
#define SEQ     1024
#define TOKENS  (BATCHSZ*SEQ)     // 8192
#define BHT     (BATCHSZ*HEADS)   // 96

// ---------------- scratch ----------------------------------------------------
__device__ float g_h   [(size_t)TOKENS*EMBED];
__device__ float g_qkv [(size_t)TOKENS*3*EMBED];
__device__ float g_S   [(size_t)BHT*SEQ*SEQ];
__device__ float g_attn[(size_t)TOKENS*EMBED];
__device__ float g_x2  [(size_t)TOKENS*EMBED];
__device__ float g_h2  [(size_t)TOKENS*EMBED];
__device__ float g_hid [(size_t)TOKENS*HIDDEN];

// ---------------- LayerNorm ---------------------------------------------------
__global__ void ln_kernel(const float* __restrict__ x,
                          const float* __restrict__ g,
                          const float* __restrict__ b,
                          float* __restrict__ out) {
    int row = blockIdx.x;
    const float* xr = x + (size_t)row * EMBED;
    float s = 0.f, s2 = 0.f;
    for (int i = threadIdx.x; i < EMBED; i += blockDim.x) {
        float v = xr[i]; s += v; s2 += v * v;
    }
    __shared__ float red[64];
    int wid = threadIdx.x >> 5, lid = threadIdx.x & 31;
    #pragma unroll
    for (int o = 16; o; o >>= 1) {
        s  += __shfl_down_sync(0xffffffffu, s,  o);
        s2 += __shfl_down_sync(0xffffffffu, s2, o);
    }
    if (lid == 0) { red[wid] = s; red[wid + 32] = s2; }
    __syncthreads();
    if (wid == 0) {
        int nw = blockDim.x >> 5;
        s  = (lid < nw) ? red[lid]      : 0.f;
        s2 = (lid < nw) ? red[lid + 32] : 0.f;
        #pragma unroll
        for (int o = 16; o; o >>= 1) {
            s  += __shfl_down_sync(0xffffffffu, s,  o);
            s2 += __shfl_down_sync(0xffffffffu, s2, o);
        }
        if (lid == 0) { red[0] = s; red[1] = s2; }
    }
    __syncthreads();
    float mu  = red[0] * (1.f / EMBED);
    float var = red[1] * (1.f / EMBED) - mu * mu;
    float rstd = rsqrtf(var + 1e-5f);
    float* o = out + (size_t)row * EMBED;
    for (int i = threadIdx.x; i < EMBED; i += blockDim.x)
        o[i] = (xr[i] - mu) * rstd * g[i] + b[i];
}

// ---------------- row softmax --------------------------------------------------
__global__ void softmax_kernel(float* __restrict__ S) {
    size_t row = blockIdx.x;
    float* r = S + row * SEQ;
    int wid = threadIdx.x >> 5, lid = threadIdx.x & 31;
    int nw = blockDim.x >> 5;
    __shared__ float red[32];

    float m = -1e30f;
    for (int i = threadIdx.x; i < SEQ; i += blockDim.x) m = fmaxf(m, r[i]);
    #pragma unroll
    for (int o = 16; o; o >>= 1) m = fmaxf(m, __shfl_xor_sync(0xffffffffu, m, o));
    if (lid == 0) red[wid] = m;
    __syncthreads();
    if (threadIdx.x < 32) {
        float t = (lid < nw) ? red[lid] : -1e30f;
        #pragma unroll
        for (int o = 16; o; o >>= 1) t = fmaxf(t, __shfl_xor_sync(0xffffffffu, t, o));
        if (lid == 0) red[0] = t;
    }
    __syncthreads();
    m = red[0];
    __syncthreads();

    float s = 0.f;
    for (int i = threadIdx.x; i < SEQ; i += blockDim.x) {
        float e = __expf(r[i] - m);
        r[i] = e;
        s += e;
    }
    #pragma unroll
    for (int o = 16; o; o >>= 1) s += __shfl_xor_sync(0xffffffffu, s, o);
    if (lid == 0) red[wid] = s;
    __syncthreads();
    if (threadIdx.x < 32) {
        float t = (lid < nw) ? red[lid] : 0.f;
        #pragma unroll
        for (int o = 16; o; o >>= 1) t += __shfl_xor_sync(0xffffffffu, t, o);
        if (lid == 0) red[0] = t;
    }
    __syncthreads();
    float inv = 1.f / red[0];
    for (int i = threadIdx.x; i < SEQ; i += blockDim.x) r[i] *= inv;
}

// ---------------- tf32 helpers --------------------------------------------------
__device__ __forceinline__ float tf32cvt(float x) {
    uint32_t u;
    asm("cvt.rna.tf32.f32 %0, %1;" : "=r"(u) : "f"(x));
    return __uint_as_float(u);
}

__device__ __forceinline__ void mma_tf32(float c[4],
                                         uint32_t a0, uint32_t a1, uint32_t a2, uint32_t a3,
                                         uint32_t b0, uint32_t b1) {
    asm volatile(
        "mma.sync.aligned.m16n8k8.row.col.f32.tf32.tf32.f32 "
        "{%0,%1,%2,%3}, {%4,%5,%6,%7}, {%8,%9}, {%0,%1,%2,%3};"
        : "+f"(c[0]), "+f"(c[1]), "+f"(c[2]), "+f"(c[3])
        : "r"(a0), "r"(a1), "r"(a2), "r"(a3), "r"(b0), "r"(b1));
}

// ---------------- tensor-core GEMM ----------------------------------------------
template<int BM, int BN, int BK, bool TRANSB, bool GELU>
__global__ void __launch_bounds__(256)
gemm_tc(const float* __restrict__ A, const float* __restrict__ B,
        float* __restrict__ C,
        int M, int N, int K, int lda, int ldb, int ldc,
        long long sA1, long long sA2,
        long long sB1, long long sB2,
        long long sC1, long long sC2, int HB,
        float alpha,
        const float* __restrict__ bias,
        const float* __restrict__ res) {
    static_assert(BM == 128 && BK == 16, "fixed");
    constexpr int WN  = BN / 2;                        // warp cols
    constexpr int NT  = WN / 8;                        // n8 tiles per warp
    constexpr int AS  = BK + 4;                        // A smem row stride
    constexpr int BSS = TRANSB ? (BK + 4) : (BN + 8);  // B smem row stride
    constexpr int B_ROWS = TRANSB ? BN : BK;
    constexpr int NAF = (BM * BK) / (4 * 256);         // 2 float4/thread for A
    constexpr int NBF = (B_ROWS * BK * (TRANSB ? 1 : BN / BK)) / (4 * 256) > 0
                        ? (TRANSB ? (BN * BK) / (4 * 256) : (BK * BN) / (4 * 256))
                        : 1;

    __shared__ float As[2][BM * AS];
    __shared__ float Bs[2][B_ROWS * BSS];

    const int tid = threadIdx.x;
    const int warp = tid >> 5, lane = tid & 31;
    const int gid = lane >> 2, tig = lane & 3;
    const int wm = warp >> 1, wn = warp & 1;

    const int z = blockIdx.z;
    const int zb = z / HB, zh = z % HB;
    A += (size_t)zb * sA1 + (size_t)zh * sA2;
    B += (size_t)zb * sB1 + (size_t)zh * sB2;
    C += (size_t)zb * sC1 + (size_t)zh * sC2;
    const float* resp = res;
    if (resp) resp += (size_t)zb * sC1 + (size_t)zh * sC2;

    const int m0 = blockIdx.y * BM;
    const int n0 = blockIdx.x * BN;

    float acc[2][NT][4];
    #pragma unroll
    for (int mi = 0; mi < 2; mi++)
        #pragma unroll
        for (int ni = 0; ni < NT; ni++)
            #pragma unroll
            for (int q = 0; q < 4; q++) acc[mi][ni][q] = 0.f;

    float4 ra[NAF];
    float4 rb[NBF];

    const int niter = K / BK;

    // ---- global load into registers ----
    auto load_g = [&](int it) {
        const int k0 = it * BK;
        #pragma unroll
        for (int i = 0; i < NAF; i++) {
            int s = tid + i * 256;
            int m = s >> 2, c = s & 3;
            ra[i] = *reinterpret_cast<const float4*>(A + (size_t)(m0 + m) * lda + k0 + 4 * c);
        }
        #pragma unroll
        for (int i = 0; i < NBF; i++) {
            int s = tid + i * 256;
            if (TRANSB) {
                int n = s >> 2, c = s & 3;
                rb[i] = *reinterpret_cast<const float4*>(B + (size_t)(n0 + n) * ldb + k0 + 4 * c);
            } else {
                int n4 = s & (BN / 4 - 1), k = s / (BN / 4);
                rb[i] = *reinterpret_cast<const float4*>(B + (size_t)(k0 + k) * ldb + n0 + 4 * n4);
            }
        }
    };

    // ---- cvt + store to smem ----
    auto store_s = [&](int buf) {
        #pragma unroll
        for (int i = 0; i < NAF; i++) {
            int s = tid + i * 256;
            int m = s >> 2, c = s & 3;
            float4 v = ra[i];
            float4 w = make_float4(tf32cvt(v.x), tf32cvt(v.y), tf32cvt(v.z), tf32cvt(v.w));
            *reinterpret_cast<float4*>(&As[buf][m * AS + 4 * c]) = w;
        }
        #pragma unroll
        for (int i = 0; i < NBF; i++) {
            int s = tid + i * 256;
            float4 v = rb[i];
            float4 w = make_float4(tf32cvt(v.x), tf32cvt(v.y), tf32cvt(v.z), tf32cvt(v.w));
            if (TRANSB) {
                int n = s >> 2, c = s & 3;
                *reinterpret_cast<float4*>(&Bs[buf][n * BSS + 4 * c]) = w;
            } else {
                int n4 = s & (BN / 4 - 1), k = s / (BN / 4);
                *reinterpret_cast<float4*>(&Bs[buf][k * BSS + 4 * n4]) = w;
            }
        }
    };

    load_g(0);
    store_s(0);
    __syncthreads();

    for (int it = 0; it < niter; ++it) {
        const int cur = it & 1;
        if (it + 1 < niter) load_g(it + 1);

        #pragma unroll
        for (int ks = 0; ks < BK / 8; ks++) {
            const int k = ks * 8;
            uint32_t afr[2][4];
            #pragma unroll
            for (int mi = 0; mi < 2; mi++) {
                int rbse = wm * 32 + mi * 16;
                afr[mi][0] = __float_as_uint(As[cur][(rbse + gid)     * AS + k + tig]);
                afr[mi][1] = __float_as_uint(As[cur][(rbse + gid + 8) * AS + k + tig]);
                afr[mi][2] = __float_as_uint(As[cur][(rbse + gid)     * AS + k + tig + 4]);
                afr[mi][3] = __float_as_uint(As[cur][(rbse + gid + 8) * AS + k + tig + 4]);
            }
            uint32_t bfr[NT][2];
            #pragma unroll
            for (int ni = 0; ni < NT; ni++) {
                int col = wn * WN + ni * 8 + gid;
                if (TRANSB) {
                    bfr[ni][0] = __float_as_uint(Bs[cur][col * BSS + k + tig]);
                    bfr[ni][1] = __float_as_uint(Bs[cur][col * BSS + k + tig + 4]);
                } else {
                    bfr[ni][0] = __float_as_uint(Bs[cur][(k + tig)     * BSS + col]);
                    bfr[ni][1] = __float_as_uint(Bs[cur][(k + tig + 4) * BSS + col]);
                }
            }
            #pragma unroll
            for (int mi = 0; mi < 2; mi++)
                #pragma unroll
                for (int ni = 0; ni < NT; ni++)
                    mma_tf32(acc[mi][ni], afr[mi][0], afr[mi][1], afr[mi][2], afr[mi][3],
                             bfr[ni][0], bfr[ni][1]);
        }

        if (it + 1 < niter) store_s(cur ^ 1);
        __syncthreads();
    }

    // ---- epilogue ----
    #pragma unroll
    for (int mi = 0; mi < 2; mi++) {
        #pragma unroll
        for (int ni = 0; ni < NT; ni++) {
            int row = m0 + wm * 32 + mi * 16 + gid;
            int col = n0 + wn * WN + ni * 8 + tig * 2;
            float v0 = acc[mi][ni][0] * alpha;
            float v1 = acc[mi][ni][1] * alpha;
            float v2 = acc[mi][ni][2] * alpha;
            float v3 = acc[mi][ni][3] * alpha;
            if (bias) {
                float bb0 = bias[col], bb1 = bias[col + 1];
                v0 += bb0; v1 += bb1; v2 += bb0; v3 += bb1;
            }
            if (GELU) {
                v0 = 0.5f * v0 * (1.f + erff(v0 * 0.70710678118654752f));
                v1 = 0.5f * v1 * (1.f + erff(v1 * 0.70710678118654752f));
                v2 = 0.5f * v2 * (1.f + erff(v2 * 0.70710678118654752f));
                v3 = 0.5f * v3 * (1.f + erff(v3 * 0.70710678118654752f));
            }
            if (resp) {
                const float2 r0 = *reinterpret_cast<const float2*>(resp + (size_t)row * ldc + col);
                const float2 r1 = *reinterpret_cast<const float2*>(resp + (size_t)(row + 8) * ldc + col);
                v0 += r0.x; v1 += r0.y; v2 += r1.x; v3 += r1.y;
            }
            *reinterpret_cast<float2*>(C + (size_t)row * ldc + col)       = make_float2(v0, v1);
            *reinterpret_cast<float2*>(C + (size_t)(row + 8) * ldc + col) = make_float2(v2, v3);
        }
    }
}

// ---------------- launch ---------------------------------------------------------
extern "C" void kernel_launch(void* const* d_in, const int* in_sizes, int n_in,
                              void* d_out, int out_size) {
    const float* x      = (const float*)d_in[0];
    const float* g1     = (const float*)d_in[1];
    const float* b1     = (const float*)d_in[2];
    const float* g2     = (const float*)d_in[3];
    const float* b2     = (const float*)d_in[4];
    const float* w_qkv  = (const float*)d_in[5];
    const float* w_proj = (const float*)d_in[6];
    const float* b_proj = (const float*)d_in[7];
    const float* w_fc1  = (const float*)d_in[8];
    const float* b_fc1  = (const float*)d_in[9];
    const float* w_fc2  = (const float*)d_in[10];
    const float* b_fc2  = (const float*)d_in[11];
    float* out = (float*)d_out;

    float *p_h, *p_qkv, *p_S, *p_attn, *p_x2, *p_h2, *p_hid;
    cudaGetSymbolAddress((void**)&p_h,    g_h);
    cudaGetSymbolAddress((void**)&p_qkv,  g_qkv);
    cudaGetSymbolAddress((void**)&p_S,    g_S);
    cudaGetSymbolAddress((void**)&p_attn, g_attn);
    cudaGetSymbolAddress((void**)&p_x2,   g_x2);
    cudaGetSymbolAddress((void**)&p_h2,   g_h2);
    cudaGetSymbolAddress((void**)&p_hid,  g_hid);

    const long long ZL = 0;

    ln_kernel<<<TOKENS, 256>>>(x, g1, b1, p_h);

    gemm_tc<128,128,16,false,false>
        <<<dim3(3*EMBED/128, TOKENS/128, 1), 256>>>(
        p_h, w_qkv, p_qkv,
        TOKENS, 3*EMBED, EMBED, EMBED, 3*EMBED, 3*EMBED,
        ZL, ZL, ZL, ZL, ZL, ZL, 1, 1.f, nullptr, nullptr);

    gemm_tc<128,128,16,true,false>
        <<<dim3(SEQ/128, SEQ/128, BHT), 256>>>(
        p_qkv, p_qkv + EMBED, p_S,
        SEQ, SEQ, HDIM, 3*EMBED, 3*EMBED, SEQ,
        (long long)SEQ*3*EMBED, (long long)HDIM,
        (long long)SEQ*3*EMBED, (long long)HDIM,
        (long long)HEADS*SEQ*SEQ, (long long)SEQ*SEQ,
        HEADS, 0.125f, nullptr, nullptr);

    softmax_kernel<<<BHT*SEQ, 256>>>(p_S);

    gemm_tc<128,64,16,false,false>
        <<<dim3(1, SEQ/128, BHT), 256>>>(
        p_S, p_qkv + 2*EMBED, p_attn,
        SEQ, HDIM, SEQ, SEQ, 3*EMBED, EMBED,
        (long long)HEADS*SEQ*SEQ, (long long)SEQ*SEQ,
        (long long)SEQ*3*EMBED, (long long)HDIM,
        (long long)SEQ*EMBED, (long long)HDIM,
        HEADS, 1.f, nullptr, nullptr);

    gemm_tc<128,128,16,false,false>
        <<<dim3(EMBED/128, TOKENS/128, 1), 256>>>(
        p_attn, w_proj, p_x2,
        TOKENS, EMBED, EMBED, EMBED, EMBED, EMBED,
        ZL, ZL, ZL, ZL, ZL, ZL, 1, 1.f, b_proj, x);

    ln_kernel<<<TOKENS, 256>>>(p_x2, g2, b2, p_h2);

    gemm_tc<128,128,16,false,true>
        <<<dim3(HIDDEN/128, TOKENS/128, 1), 256>>>(
        p_h2, w_fc1, p_hid,
        TOKENS, HIDDEN, EMBED, EMBED, HIDDEN, HIDDEN,
        ZL, ZL, ZL, ZL, ZL, ZL, 1, 1.f, b_fc1, nullptr);

    gemm_tc<128,128,16,false,false>
        <<<dim3(EMBED/128, TOKENS/128, 1), 256>>>(
        p_hid, w_fc2, out,
        TOKENS, EMBED, HIDDEN, HIDDEN, EMBED, EMBED,
        ZL, ZL, ZL, ZL, ZL, ZL, 1, 1.f, b_fc2, p_x2);
}

// round 3
// speedup vs baseline: 3.1563x; 1.1609x over previous
#include <cuda_runtime.h>
#include <math.h>
#include <stdint.h>

#define EMBED   768
#define HEADS   12
#define HDIM    64
#define HIDDEN  3072
#define BATCHSZ 8
#define SEQ     1024
#define TOKENS  (BATCHSZ*SEQ)     // 8192
#define BHT     (BATCHSZ*HEADS)   // 96

// ---------------- scratch ----------------------------------------------------
__device__ float g_h   [(size_t)TOKENS*EMBED];
__device__ float g_qkv [(size_t)TOKENS*3*EMBED];
__device__ float g_attn[(size_t)TOKENS*EMBED];
__device__ float g_x2  [(size_t)TOKENS*EMBED];
__device__ float g_h2  [(size_t)TOKENS*EMBED];
__device__ float g_hid [(size_t)TOKENS*HIDDEN];

// ---------------- LayerNorm ---------------------------------------------------
__global__ void ln_kernel(const float* __restrict__ x,
                          const float* __restrict__ g,
                          const float* __restrict__ b,
                          float* __restrict__ out) {
    int row = blockIdx.x;
    const float* xr = x + (size_t)row * EMBED;
    float s = 0.f, s2 = 0.f;
    for (int i = threadIdx.x; i < EMBED; i += blockDim.x) {
        float v = xr[i]; s += v; s2 += v * v;
    }
    __shared__ float red[64];
    int wid = threadIdx.x >> 5, lid = threadIdx.x & 31;
    #pragma unroll
    for (int o = 16; o; o >>= 1) {
        s  += __shfl_down_sync(0xffffffffu, s,  o);
        s2 += __shfl_down_sync(0xffffffffu, s2, o);
    }
    if (lid == 0) { red[wid] = s; red[wid + 32] = s2; }
    __syncthreads();
    if (wid == 0) {
        int nw = blockDim.x >> 5;
        s  = (lid < nw) ? red[lid]      : 0.f;
        s2 = (lid < nw) ? red[lid + 32] : 0.f;
        #pragma unroll
        for (int o = 16; o; o >>= 1) {
            s  += __shfl_down_sync(0xffffffffu, s,  o);
            s2 += __shfl_down_sync(0xffffffffu, s2, o);
        }
        if (lid == 0) { red[0] = s; red[1] = s2; }
    }
    __syncthreads();
    float mu  = red[0] * (1.f / EMBED);
    float var = red[1] * (1.f / EMBED) - mu * mu;
    float rstd = rsqrtf(var + 1e-5f);
    float* o = out + (size_t)row * EMBED;
    for (int i = threadIdx.x; i < EMBED; i += blockDim.x)
        o[i] = (xr[i] - mu) * rstd * g[i] + b[i];
}

// ---------------- tf32 helpers --------------------------------------------------
__device__ __forceinline__ float tf32cvt(float x) {
    uint32_t u;
    asm("cvt.rna.tf32.f32 %0, %1;" : "=r"(u) : "f"(x));
    return __uint_as_float(u);
}

__device__ __forceinline__ void mma_tf32(float c[4],
                                         uint32_t a0, uint32_t a1, uint32_t a2, uint32_t a3,
                                         uint32_t b0, uint32_t b1) {
    asm volatile(
        "mma.sync.aligned.m16n8k8.row.col.f32.tf32.tf32.f32 "
        "{%0,%1,%2,%3}, {%4,%5,%6,%7}, {%8,%9}, {%0,%1,%2,%3};"
        : "+f"(c[0]), "+f"(c[1]), "+f"(c[2]), "+f"(c[3])
        : "r"(a0), "r"(a1), "r"(a2), "r"(a3), "r"(b0), "r"(b1));
}

// ---------------- fused flash attention ------------------------------------------
// One CTA = 128 Q rows of one (batch, head). 8 warps; warp w owns rows w*16..w*16+15.
// Loop over 8 KV tiles of 128 tokens: S = (Q*0.125) K^T via mma, online softmax,
// P staged to per-warp smem (tf32), O += P V via mma. S never touches HBM.
#define BQ  128
#define BKV 128
#define QS_ST 68   // HDIM + 4
#define KS_ST 68
#define VS_ST 72
#define PS_ST 132

__global__ void __launch_bounds__(256)
flash_kernel(const float* __restrict__ qkv, float* __restrict__ attn) {
    extern __shared__ float sm[];
    float* Qs = sm;                       // 128*68
    float* Ks = Qs + BQ * QS_ST;          // 128*68
    float* Vs = Ks + BKV * KS_ST;         // 128*72
    float* Ps = Vs + BKV * VS_ST;         // 8*16*132

    const int tid  = threadIdx.x;
    const int warp = tid >> 5, lane = tid & 31;
    const int gid  = lane >> 2, tig = lane & 3;
    const int bh = blockIdx.y;
    const int b  = bh / HEADS, h = bh % HEADS;
    const int q0 = blockIdx.x * BQ;
    const int wrow = warp * 16;
    float* Pw = Ps + warp * 16 * PS_ST;

    const float* qbase = qkv + ((size_t)b * SEQ) * 3 * EMBED + h * HDIM;
    const float* kbase = qbase + EMBED;
    const float* vbase = qbase + 2 * EMBED;

    // ---- load Q tile (scale by 0.125, tf32) ----
    #pragma unroll
    for (int i = 0; i < 8; i++) {
        int s = tid + i * 256;
        int r = s >> 4, c = (s & 15) * 4;
        float4 v = *reinterpret_cast<const float4*>(qbase + (size_t)(q0 + r) * 3 * EMBED + c);
        float4 w = make_float4(tf32cvt(v.x * 0.125f), tf32cvt(v.y * 0.125f),
                               tf32cvt(v.z * 0.125f), tf32cvt(v.w * 0.125f));
        *reinterpret_cast<float4*>(&Qs[r * QS_ST + c]) = w;
    }

    float m0 = -1e30f, m1 = -1e30f, l0 = 0.f, l1 = 0.f;
    float oacc[8][4];
    #pragma unroll
    for (int ni = 0; ni < 8; ni++)
        #pragma unroll
        for (int q = 0; q < 4; q++) oacc[ni][q] = 0.f;

    for (int t = 0; t < SEQ / BKV; t++) {
        __syncthreads();   // prev iter's K/V reads done (also covers Q-store on t=0)
        // ---- load K,V tiles (tf32) ----
        #pragma unroll
        for (int i = 0; i < 8; i++) {
            int s = tid + i * 256;
            int r = s >> 4, c = (s & 15) * 4;
            size_t row_off = (size_t)(t * BKV + r) * 3 * EMBED + c;
            float4 kv = *reinterpret_cast<const float4*>(kbase + row_off);
            float4 vv = *reinterpret_cast<const float4*>(vbase + row_off);
            *reinterpret_cast<float4*>(&Ks[r * KS_ST + c]) =
                make_float4(tf32cvt(kv.x), tf32cvt(kv.y), tf32cvt(kv.z), tf32cvt(kv.w));
            *reinterpret_cast<float4*>(&Vs[r * VS_ST + c]) =
                make_float4(tf32cvt(vv.x), tf32cvt(vv.y), tf32cvt(vv.z), tf32cvt(vv.w));
        }
        __syncthreads();

        // ---- S = Qs @ Ks^T  (per warp: 16 x 128) ----
        float sacc[16][4];
        #pragma unroll
        for (int ni = 0; ni < 16; ni++)
            #pragma unroll
            for (int q = 0; q < 4; q++) sacc[ni][q] = 0.f;

        #pragma unroll
        for (int ks = 0; ks < 8; ks++) {
            const int k = ks * 8;
            uint32_t a0 = __float_as_uint(Qs[(wrow + gid)     * QS_ST + k + tig]);
            uint32_t a1 = __float_as_uint(Qs[(wrow + gid + 8) * QS_ST + k + tig]);
            uint32_t a2 = __float_as_uint(Qs[(wrow + gid)     * QS_ST + k + tig + 4]);
            uint32_t a3 = __float_as_uint(Qs[(wrow + gid + 8) * QS_ST + k + tig + 4]);
            #pragma unroll
            for (int ni = 0; ni < 16; ni++) {
                uint32_t b0 = __float_as_uint(Ks[(ni * 8 + gid) * KS_ST + k + tig]);
                uint32_t b1 = __float_as_uint(Ks[(ni * 8 + gid) * KS_ST + k + tig + 4]);
                mma_tf32(sacc[ni], a0, a1, a2, a3, b0, b1);
            }
        }

        // ---- online softmax (rows gid / gid+8 of this warp) ----
        float rmax0 = -1e30f, rmax1 = -1e30f;
        #pragma unroll
        for (int ni = 0; ni < 16; ni++) {
            rmax0 = fmaxf(rmax0, fmaxf(sacc[ni][0], sacc[ni][1]));
            rmax1 = fmaxf(rmax1, fmaxf(sacc[ni][2], sacc[ni][3]));
        }
        #pragma unroll
        for (int o = 1; o <= 2; o <<= 1) {
            rmax0 = fmaxf(rmax0, __shfl_xor_sync(0xffffffffu, rmax0, o));
            rmax1 = fmaxf(rmax1, __shfl_xor_sync(0xffffffffu, rmax1, o));
        }
        float mn0 = fmaxf(m0, rmax0);
        float mn1 = fmaxf(m1, rmax1);
        float sf0 = __expf(m0 - mn0);
        float sf1 = __expf(m1 - mn1);

        float rs0 = 0.f, rs1 = 0.f;
        #pragma unroll
        for (int ni = 0; ni < 16; ni++) {
            float p0 = __expf(sacc[ni][0] - mn0);
            float p1 = __expf(sacc[ni][1] - mn0);
            float p2 = __expf(sacc[ni][2] - mn1);
            float p3 = __expf(sacc[ni][3] - mn1);
            rs0 += p0 + p1;
            rs1 += p2 + p3;
            int cc = ni * 8 + tig * 2;
            *reinterpret_cast<float2*>(&Pw[gid * PS_ST + cc]) =
                make_float2(tf32cvt(p0), tf32cvt(p1));
            *reinterpret_cast<float2*>(&Pw[(gid + 8) * PS_ST + cc]) =
                make_float2(tf32cvt(p2), tf32cvt(p3));
        }
        #pragma unroll
        for (int o = 1; o <= 2; o <<= 1) {
            rs0 += __shfl_xor_sync(0xffffffffu, rs0, o);
            rs1 += __shfl_xor_sync(0xffffffffu, rs1, o);
        }
        l0 = l0 * sf0 + rs0;
        l1 = l1 * sf1 + rs1;
        m0 = mn0;
        m1 = mn1;

        #pragma unroll
        for (int ni = 0; ni < 8; ni++) {
            oacc[ni][0] *= sf0; oacc[ni][1] *= sf0;
            oacc[ni][2] *= sf1; oacc[ni][3] *= sf1;
        }
        __syncwarp();   // P visible within warp

        // ---- O += P @ V  (per warp: 16 x 64, K = 128) ----
        #pragma unroll
        for (int ks = 0; ks < 16; ks++) {
            const int k = ks * 8;
            uint32_t a0 = __float_as_uint(Pw[gid * PS_ST + k + tig]);
            uint32_t a1 = __float_as_uint(Pw[(gid + 8) * PS_ST + k + tig]);
            uint32_t a2 = __float_as_uint(Pw[gid * PS_ST + k + tig + 4]);
            uint32_t a3 = __float_as_uint(Pw[(gid + 8) * PS_ST + k + tig + 4]);
            #pragma unroll
            for (int ni = 0; ni < 8; ni++) {
                uint32_t b0 = __float_as_uint(Vs[(k + tig)     * VS_ST + ni * 8 + gid]);
                uint32_t b1 = __float_as_uint(Vs[(k + tig + 4) * VS_ST + ni * 8 + gid]);
                mma_tf32(oacc[ni], a0, a1, a2, a3, b0, b1);
            }
        }
    }

    // ---- finalize and write ----
    float inv0 = 1.f / l0;
    float inv1 = 1.f / l1;
    const int tok0 = b * SEQ + q0 + wrow;
    #pragma unroll
    for (int ni = 0; ni < 8; ni++) {
        int col = h * HDIM + ni * 8 + tig * 2;
        *reinterpret_cast<float2*>(attn + (size_t)(tok0 + gid) * EMBED + col) =
            make_float2(oacc[ni][0] * inv0, oacc[ni][1] * inv0);
        *reinterpret_cast<float2*>(attn + (size_t)(tok0 + gid + 8) * EMBED + col) =
            make_float2(oacc[ni][2] * inv1, oacc[ni][3] * inv1);
    }
}

// ---------------- tensor-core GEMM ----------------------------------------------
template<int BM, int BN, int BK, bool TRANSB, bool GELU>
__global__ void __launch_bounds__(256, 2)
gemm_tc(const float* __restrict__ A, const float* __restrict__ B,
        float* __restrict__ C,
        int M, int N, int K, int lda, int ldb, int ldc,
        float alpha,
        const float* __restrict__ bias,
        const float* __restrict__ res) {
    static_assert(BM == 128 && BK == 16, "fixed");
    constexpr int WN  = BN / 2;
    constexpr int NT  = WN / 8;
    constexpr int AS  = BK + 4;
    constexpr int BSS = TRANSB ? (BK + 4) : (BN + 8);
    constexpr int B_ROWS = TRANSB ? BN : BK;
    constexpr int NAF = (BM * BK) / (4 * 256);
    constexpr int NBF = TRANSB ? (BN * BK) / (4 * 256) : (BK * BN) / (4 * 256);

    __shared__ float As[2][BM * AS];
    __shared__ float Bs[2][B_ROWS * BSS];

    const int tid = threadIdx.x;
    const int warp = tid >> 5, lane = tid & 31;
    const int gid = lane >> 2, tig = lane & 3;
    const int wm = warp >> 1, wn = warp & 1;

    const int m0 = blockIdx.y * BM;
    const int n0 = blockIdx.x * BN;

    float acc[2][NT][4];
    #pragma unroll
    for (int mi = 0; mi < 2; mi++)
        #pragma unroll
        for (int ni = 0; ni < NT; ni++)
            #pragma unroll
            for (int q = 0; q < 4; q++) acc[mi][ni][q] = 0.f;

    float4 ra[NAF];
    float4 rb[NBF];

    const int niter = K / BK;

    auto load_g = [&](int it) {
        const int k0 = it * BK;
        #pragma unroll
        for (int i = 0; i < NAF; i++) {
            int s = tid + i * 256;
            int m = s >> 2, c = s & 3;
            ra[i] = *reinterpret_cast<const float4*>(A + (size_t)(m0 + m) * lda + k0 + 4 * c);
        }
        #pragma unroll
        for (int i = 0; i < NBF; i++) {
            int s = tid + i * 256;
            if (TRANSB) {
                int n = s >> 2, c = s & 3;
                rb[i] = *reinterpret_cast<const float4*>(B + (size_t)(n0 + n) * ldb + k0 + 4 * c);
            } else {
                int n4 = s & (BN / 4 - 1), k = s / (BN / 4);
                rb[i] = *reinterpret_cast<const float4*>(B + (size_t)(k0 + k) * ldb + n0 + 4 * n4);
            }
        }
    };

    auto store_s = [&](int buf) {
        #pragma unroll
        for (int i = 0; i < NAF; i++) {
            int s = tid + i * 256;
            int m = s >> 2, c = s & 3;
            float4 v = ra[i];
            float4 w = make_float4(tf32cvt(v.x), tf32cvt(v.y), tf32cvt(v.z), tf32cvt(v.w));
            *reinterpret_cast<float4*>(&As[buf][m * AS + 4 * c]) = w;
        }
        #pragma unroll
        for (int i = 0; i < NBF; i++) {
            int s = tid + i * 256;
            float4 v = rb[i];
            float4 w = make_float4(tf32cvt(v.x), tf32cvt(v.y), tf32cvt(v.z), tf32cvt(v.w));
            if (TRANSB) {
                int n = s >> 2, c = s & 3;
                *reinterpret_cast<float4*>(&Bs[buf][n * BSS + 4 * c]) = w;
            } else {
                int n4 = s & (BN / 4 - 1), k = s / (BN / 4);
                *reinterpret_cast<float4*>(&Bs[buf][k * BSS + 4 * n4]) = w;
            }
        }
    };

    load_g(0);
    store_s(0);
    __syncthreads();

    for (int it = 0; it < niter; ++it) {
        const int cur = it & 1;
        if (it + 1 < niter) load_g(it + 1);

        #pragma unroll
        for (int ks = 0; ks < BK / 8; ks++) {
            const int k = ks * 8;
            uint32_t afr[2][4];
            #pragma unroll
            for (int mi = 0; mi < 2; mi++) {
                int rbse = wm * 32 + mi * 16;
                afr[mi][0] = __float_as_uint(As[cur][(rbse + gid)     * AS + k + tig]);
                afr[mi][1] = __float_as_uint(As[cur][(rbse + gid + 8) * AS + k + tig]);
                afr[mi][2] = __float_as_uint(As[cur][(rbse + gid)     * AS + k + tig + 4]);
                afr[mi][3] = __float_as_uint(As[cur][(rbse + gid + 8) * AS + k + tig + 4]);
            }
            uint32_t bfr[NT][2];
            #pragma unroll
            for (int ni = 0; ni < NT; ni++) {
                int col = wn * WN + ni * 8 + gid;
                if (TRANSB) {
                    bfr[ni][0] = __float_as_uint(Bs[cur][col * BSS + k + tig]);
                    bfr[ni][1] = __float_as_uint(Bs[cur][col * BSS + k + tig + 4]);
                } else {
                    bfr[ni][0] = __float_as_uint(Bs[cur][(k + tig)     * BSS + col]);
                    bfr[ni][1] = __float_as_uint(Bs[cur][(k + tig + 4) * BSS + col]);
                }
            }
            #pragma unroll
            for (int mi = 0; mi < 2; mi++)
                #pragma unroll
                for (int ni = 0; ni < NT; ni++)
                    mma_tf32(acc[mi][ni], afr[mi][0], afr[mi][1], afr[mi][2], afr[mi][3],
                             bfr[ni][0], bfr[ni][1]);
        }

        if (it + 1 < niter) store_s(cur ^ 1);
        __syncthreads();
    }

    #pragma unroll
    for (int mi = 0; mi < 2; mi++) {
        #pragma unroll
        for (int ni = 0; ni < NT; ni++) {
            int row = m0 + wm * 32 + mi * 16 + gid;
            int col = n0 + wn * WN + ni * 8 + tig * 2;
            float v0 = acc[mi][ni][0] * alpha;
            float v1 = acc[mi][ni][1] * alpha;
            float v2 = acc[mi][ni][2] * alpha;
            float v3 = acc[mi][ni][3] * alpha;
            if (bias) {
                float bb0 = bias[col], bb1 = bias[col + 1];
                v0 += bb0; v1 += bb1; v2 += bb0; v3 += bb1;
            }
            if (GELU) {
                v0 = 0.5f * v0 * (1.f + erff(v0 * 0.70710678118654752f));
                v1 = 0.5f * v1 * (1.f + erff(v1 * 0.70710678118654752f));
                v2 = 0.5f * v2 * (1.f + erff(v2 * 0.70710678118654752f));
                v3 = 0.5f * v3 * (1.f + erff(v3 * 0.70710678118654752f));
            }
            if (res) {
                const float2 r0 = *reinterpret_cast<const float2*>(res + (size_t)row * ldc + col);
                const float2 r1 = *reinterpret_cast<const float2*>(res + (size_t)(row + 8) * ldc + col);
                v0 += r0.x; v1 += r0.y; v2 += r1.x; v3 += r1.y;
            }
            *reinterpret_cast<float2*>(C + (size_t)row * ldc + col)       = make_float2(v0, v1);
            *reinterpret_cast<float2*>(C + (size_t)(row + 8) * ldc + col) = make_float2(v2, v3);
        }
    }
}

// ---------------- launch ---------------------------------------------------------
extern "C" void kernel_launch(void* const* d_in, const int* in_sizes, int n_in,
                              void* d_out, int out_size) {
    const float* x      = (const float*)d_in[0];
    const float* g1     = (const float*)d_in[1];
    const float* b1     = (const float*)d_in[2];
    const float* g2     = (const float*)d_in[3];
    const float* b2     = (const float*)d_in[4];
    const float* w_qkv  = (const float*)d_in[5];
    const float* w_proj = (const float*)d_in[6];
    const float* b_proj = (const float*)d_in[7];
    const float* w_fc1  = (const float*)d_in[8];
    const float* b_fc1  = (const float*)d_in[9];
    const float* w_fc2  = (const float*)d_in[10];
    const float* b_fc2  = (const float*)d_in[11];
    float* out = (float*)d_out;

    float *p_h, *p_qkv, *p_attn, *p_x2, *p_h2, *p_hid;
    cudaGetSymbolAddress((void**)&p_h,    g_h);
    cudaGetSymbolAddress((void**)&p_qkv,  g_qkv);
    cudaGetSymbolAddress((void**)&p_attn, g_attn);
    cudaGetSymbolAddress((void**)&p_x2,   g_x2);
    cudaGetSymbolAddress((void**)&p_h2,   g_h2);
    cudaGetSymbolAddress((void**)&p_hid,  g_hid);

    const int FLASH_SMEM = (BQ*QS_ST + BKV*KS_ST + BKV*VS_ST + 8*16*PS_ST) * 4;
    static bool attr_set = false;
    if (!attr_set) {
        cudaFuncSetAttribute(flash_kernel,
                             cudaFuncAttributeMaxDynamicSharedMemorySize, FLASH_SMEM);
        attr_set = true;
    }

    // 1) LN1
    ln_kernel<<<TOKENS, 256>>>(x, g1, b1, p_h);

    // 2) qkv = h @ w_qkv
    gemm_tc<128,128,16,false,false>
        <<<dim3(3*EMBED/128, TOKENS/128, 1), 256>>>(
        p_h, w_qkv, p_qkv,
        TOKENS, 3*EMBED, EMBED, EMBED, 3*EMBED, 3*EMBED,
        1.f, nullptr, nullptr);

    // 3-5) fused attention
    flash_kernel<<<dim3(SEQ/BQ, BHT), 256, FLASH_SMEM>>>(p_qkv, p_attn);

    // 6) x2 = attn @ w_proj + b_proj + x
    gemm_tc<128,128,16,false,false>
        <<<dim3(EMBED/128, TOKENS/128, 1), 256>>>(
        p_attn, w_proj, p_x2,
        TOKENS, EMBED, EMBED, EMBED, EMBED, EMBED,
        1.f, b_proj, x);

    // 7) LN2
    ln_kernel<<<TOKENS, 256>>>(p_x2, g2, b2, p_h2);

    // 8) hid = gelu(h2 @ w_fc1 + b_fc1)
    gemm_tc<128,128,16,false,true>
        <<<dim3(HIDDEN/128, TOKENS/128, 1), 256>>>(
        p_h2, w_fc1, p_hid,
        TOKENS, HIDDEN, EMBED, EMBED, HIDDEN, HIDDEN,
        1.f, b_fc1, nullptr);

    // 9) out = hid @ w_fc2 + b_fc2 + x2
    gemm_tc<128,128,16,false,false>
        <<<dim3(EMBED/128, TOKENS/128, 1), 256>>>(
        p_hid, w_fc2, out,
        TOKENS, EMBED, HIDDEN, HIDDEN, EMBED, EMBED,
        1.f, b_fc2, p_x2);
}

// round 4
// speedup vs baseline: 3.4045x; 1.0786x over previous
#include <cuda_runtime.h>
#include <math.h>
#include <stdint.h>

#define EMBED   768
#define HEADS   12
#define HDIM    64
#define HIDDEN  3072
#define BATCHSZ 8
#define SEQ     1024
#define TOKENS  (BATCHSZ*SEQ)     // 8192
#define BHT     (BATCHSZ*HEADS)   // 96

// ---------------- scratch ----------------------------------------------------
__device__ float g_h   [(size_t)TOKENS*EMBED];
__device__ float g_qkv [(size_t)TOKENS*3*EMBED];
__device__ float g_attn[(size_t)TOKENS*EMBED];
__device__ float g_x2  [(size_t)TOKENS*EMBED];
__device__ float g_h2  [(size_t)TOKENS*EMBED];
__device__ float g_hid [(size_t)TOKENS*HIDDEN];

// ---------------- LayerNorm ---------------------------------------------------
__global__ void ln_kernel(const float* __restrict__ x,
                          const float* __restrict__ g,
                          const float* __restrict__ b,
                          float* __restrict__ out) {
    int row = blockIdx.x;
    const float* xr = x + (size_t)row * EMBED;
    float s = 0.f, s2 = 0.f;
    for (int i = threadIdx.x; i < EMBED; i += blockDim.x) {
        float v = xr[i]; s += v; s2 += v * v;
    }
    __shared__ float red[64];
    int wid = threadIdx.x >> 5, lid = threadIdx.x & 31;
    #pragma unroll
    for (int o = 16; o; o >>= 1) {
        s  += __shfl_down_sync(0xffffffffu, s,  o);
        s2 += __shfl_down_sync(0xffffffffu, s2, o);
    }
    if (lid == 0) { red[wid] = s; red[wid + 32] = s2; }
    __syncthreads();
    if (wid == 0) {
        int nw = blockDim.x >> 5;
        s  = (lid < nw) ? red[lid]      : 0.f;
        s2 = (lid < nw) ? red[lid + 32] : 0.f;
        #pragma unroll
        for (int o = 16; o; o >>= 1) {
            s  += __shfl_down_sync(0xffffffffu, s,  o);
            s2 += __shfl_down_sync(0xffffffffu, s2, o);
        }
        if (lid == 0) { red[0] = s; red[1] = s2; }
    }
    __syncthreads();
    float mu  = red[0] * (1.f / EMBED);
    float var = red[1] * (1.f / EMBED) - mu * mu;
    float rstd = rsqrtf(var + 1e-5f);
    float* o = out + (size_t)row * EMBED;
    for (int i = threadIdx.x; i < EMBED; i += blockDim.x)
        o[i] = (xr[i] - mu) * rstd * g[i] + b[i];
}

// ---------------- mma helper -----------------------------------------------------
__device__ __forceinline__ void mma_tf32(float c[4],
                                         uint32_t a0, uint32_t a1, uint32_t a2, uint32_t a3,
                                         uint32_t b0, uint32_t b1) {
    asm volatile(
        "mma.sync.aligned.m16n8k8.row.col.f32.tf32.tf32.f32 "
        "{%0,%1,%2,%3}, {%4,%5,%6,%7}, {%8,%9}, {%0,%1,%2,%3};"
        : "+f"(c[0]), "+f"(c[1]), "+f"(c[2]), "+f"(c[3])
        : "r"(a0), "r"(a1), "r"(a2), "r"(a3), "r"(b0), "r"(b1));
}

__device__ __forceinline__ void cpasync16(uint32_t s, const void* g) {
    asm volatile("cp.async.cg.shared.global [%0], [%1], 16;" :: "r"(s), "l"(g));
}
__device__ __forceinline__ void cp_commit() {
    asm volatile("cp.async.commit_group;");
}

// ---------------- fused flash attention ------------------------------------------
#define BQ  128
#define BKV 128
#define QS_ST 68
#define KS_ST 68
#define VS_ST 72
#define PS_ST 132

__global__ void __launch_bounds__(256)
flash_kernel(const float* __restrict__ qkv, float* __restrict__ attn) {
    extern __shared__ float sm[];
    float* Qs = sm;
    float* Ks = Qs + BQ * QS_ST;
    float* Vs = Ks + BKV * KS_ST;
    float* Ps = Vs + BKV * VS_ST;

    const int tid  = threadIdx.x;
    const int warp = tid >> 5, lane = tid & 31;
    const int gid  = lane >> 2, tig = lane & 3;
    const int bh = blockIdx.y;
    const int b  = bh / HEADS, h = bh % HEADS;
    const int q0 = blockIdx.x * BQ;
    const int wrow = warp * 16;
    float* Pw = Ps + warp * 16 * PS_ST;

    const float* qbase = qkv + ((size_t)b * SEQ) * 3 * EMBED + h * HDIM;
    const float* kbase = qbase + EMBED;
    const float* vbase = qbase + 2 * EMBED;

    // ---- load Q tile (scale by 0.125) ----
    #pragma unroll
    for (int i = 0; i < 8; i++) {
        int s = tid + i * 256;
        int r = s >> 4, c = (s & 15) * 4;
        float4 v = *reinterpret_cast<const float4*>(qbase + (size_t)(q0 + r) * 3 * EMBED + c);
        *reinterpret_cast<float4*>(&Qs[r * QS_ST + c]) =
            make_float4(v.x * 0.125f, v.y * 0.125f, v.z * 0.125f, v.w * 0.125f);
    }

    float m0 = -1e30f, m1 = -1e30f, l0 = 0.f, l1 = 0.f;
    float oacc[8][4];
    #pragma unroll
    for (int ni = 0; ni < 8; ni++)
        #pragma unroll
        for (int q = 0; q < 4; q++) oacc[ni][q] = 0.f;

    for (int t = 0; t < SEQ / BKV; t++) {
        __syncthreads();
        #pragma unroll
        for (int i = 0; i < 8; i++) {
            int s = tid + i * 256;
            int r = s >> 4, c = (s & 15) * 4;
            size_t row_off = (size_t)(t * BKV + r) * 3 * EMBED + c;
            *reinterpret_cast<float4*>(&Ks[r * KS_ST + c]) =
                *reinterpret_cast<const float4*>(kbase + row_off);
            *reinterpret_cast<float4*>(&Vs[r * VS_ST + c]) =
                *reinterpret_cast<const float4*>(vbase + row_off);
        }
        __syncthreads();

        // ---- S = Qs @ Ks^T ----
        float sacc[16][4];
        #pragma unroll
        for (int ni = 0; ni < 16; ni++)
            #pragma unroll
            for (int q = 0; q < 4; q++) sacc[ni][q] = 0.f;

        #pragma unroll
        for (int ks = 0; ks < 8; ks++) {
            const int k = ks * 8;
            uint32_t a0 = __float_as_uint(Qs[(wrow + gid)     * QS_ST + k + tig]);
            uint32_t a1 = __float_as_uint(Qs[(wrow + gid + 8) * QS_ST + k + tig]);
            uint32_t a2 = __float_as_uint(Qs[(wrow + gid)     * QS_ST + k + tig + 4]);
            uint32_t a3 = __float_as_uint(Qs[(wrow + gid + 8) * QS_ST + k + tig + 4]);
            #pragma unroll
            for (int ni = 0; ni < 16; ni++) {
                uint32_t b0 = __float_as_uint(Ks[(ni * 8 + gid) * KS_ST + k + tig]);
                uint32_t b1 = __float_as_uint(Ks[(ni * 8 + gid) * KS_ST + k + tig + 4]);
                mma_tf32(sacc[ni], a0, a1, a2, a3, b0, b1);
            }
        }

        // ---- online softmax ----
        float rmax0 = -1e30f, rmax1 = -1e30f;
        #pragma unroll
        for (int ni = 0; ni < 16; ni++) {
            rmax0 = fmaxf(rmax0, fmaxf(sacc[ni][0], sacc[ni][1]));
            rmax1 = fmaxf(rmax1, fmaxf(sacc[ni][2], sacc[ni][3]));
        }
        #pragma unroll
        for (int o = 1; o <= 2; o <<= 1) {
            rmax0 = fmaxf(rmax0, __shfl_xor_sync(0xffffffffu, rmax0, o));
            rmax1 = fmaxf(rmax1, __shfl_xor_sync(0xffffffffu, rmax1, o));
        }
        float mn0 = fmaxf(m0, rmax0);
        float mn1 = fmaxf(m1, rmax1);
        float sf0 = __expf(m0 - mn0);
        float sf1 = __expf(m1 - mn1);

        float rs0 = 0.f, rs1 = 0.f;
        #pragma unroll
        for (int ni = 0; ni < 16; ni++) {
            float p0 = __expf(sacc[ni][0] - mn0);
            float p1 = __expf(sacc[ni][1] - mn0);
            float p2 = __expf(sacc[ni][2] - mn1);
            float p3 = __expf(sacc[ni][3] - mn1);
            rs0 += p0 + p1;
            rs1 += p2 + p3;
            int cc = ni * 8 + tig * 2;
            *reinterpret_cast<float2*>(&Pw[gid * PS_ST + cc])       = make_float2(p0, p1);
            *reinterpret_cast<float2*>(&Pw[(gid + 8) * PS_ST + cc]) = make_float2(p2, p3);
        }
        #pragma unroll
        for (int o = 1; o <= 2; o <<= 1) {
            rs0 += __shfl_xor_sync(0xffffffffu, rs0, o);
            rs1 += __shfl_xor_sync(0xffffffffu, rs1, o);
        }
        l0 = l0 * sf0 + rs0;
        l1 = l1 * sf1 + rs1;
        m0 = mn0;
        m1 = mn1;

        #pragma unroll
        for (int ni = 0; ni < 8; ni++) {
            oacc[ni][0] *= sf0; oacc[ni][1] *= sf0;
            oacc[ni][2] *= sf1; oacc[ni][3] *= sf1;
        }
        __syncwarp();

        // ---- O += P @ V ----
        #pragma unroll
        for (int ks = 0; ks < 16; ks++) {
            const int k = ks * 8;
            uint32_t a0 = __float_as_uint(Pw[gid * PS_ST + k + tig]);
            uint32_t a1 = __float_as_uint(Pw[(gid + 8) * PS_ST + k + tig]);
            uint32_t a2 = __float_as_uint(Pw[gid * PS_ST + k + tig + 4]);
            uint32_t a3 = __float_as_uint(Pw[(gid + 8) * PS_ST + k + tig + 4]);
            #pragma unroll
            for (int ni = 0; ni < 8; ni++) {
                uint32_t b0 = __float_as_uint(Vs[(k + tig)     * VS_ST + ni * 8 + gid]);
                uint32_t b1 = __float_as_uint(Vs[(k + tig + 4) * VS_ST + ni * 8 + gid]);
                mma_tf32(oacc[ni], a0, a1, a2, a3, b0, b1);
            }
        }
    }

    float inv0 = 1.f / l0;
    float inv1 = 1.f / l1;
    const int tok0 = b * SEQ + q0 + wrow;
    #pragma unroll
    for (int ni = 0; ni < 8; ni++) {
        int col = h * HDIM + ni * 8 + tig * 2;
        *reinterpret_cast<float2*>(attn + (size_t)(tok0 + gid) * EMBED + col) =
            make_float2(oacc[ni][0] * inv0, oacc[ni][1] * inv0);
        *reinterpret_cast<float2*>(attn + (size_t)(tok0 + gid + 8) * EMBED + col) =
            make_float2(oacc[ni][2] * inv1, oacc[ni][3] * inv1);
    }
}

// ---------------- cp.async pipelined tensor-core GEMM (NN only) -------------------
// C = A(MxK) * B(KxN) (+bias)(+GELU)(+res). 128x128x16 tiles, 3-stage cp.async.
#define GSTAGES 3
#define G_AS 20            // A smem row stride (floats)
#define G_BS 136           // B smem row stride (floats)
#define G_ASZ (128 * G_AS) // floats per A stage  (2560)
#define G_BSZ (16 * G_BS)  // floats per B stage  (2176)
#define GEMM_SMEM (GSTAGES * (G_ASZ + G_BSZ) * 4)

template<bool GELU>
__global__ void __launch_bounds__(256, 2)
gemm_cp(const float* __restrict__ A, const float* __restrict__ B,
        float* __restrict__ C,
        int K, int lda, int ldb, int ldc,
        const float* __restrict__ bias,
        const float* __restrict__ res) {
    extern __shared__ float smp[];
    float* AsB = smp;
    float* BsB = smp + GSTAGES * G_ASZ;

    const int tid = threadIdx.x;
    const int warp = tid >> 5, lane = tid & 31;
    const int gid = lane >> 2, tig = lane & 3;
    const int wm = warp >> 1, wn = warp & 1;

    const int m0 = blockIdx.y * 128;
    const int n0 = blockIdx.x * 128;

    // per-thread copy coordinates
    const int a_m  = tid >> 2,           a_kc = (tid & 3) * 4;         // +256: a_m2 = a_m+64
    const int b_k  = tid >> 5,           b_n4 = (tid & 31) * 4;        // +256: b_k2 = b_k+8

    const float* agp0 = A + (size_t)(m0 + a_m)      * lda + a_kc;
    const float* agp1 = A + (size_t)(m0 + a_m + 64) * lda + a_kc;
    const float* bgp0 = B + (size_t)b_k       * ldb + n0 + b_n4;
    const float* bgp1 = B + (size_t)(b_k + 8) * ldb + n0 + b_n4;

    const uint32_t as0 = (uint32_t)__cvta_generic_to_shared(AsB + a_m * G_AS + a_kc);
    const uint32_t as1 = (uint32_t)__cvta_generic_to_shared(AsB + (a_m + 64) * G_AS + a_kc);
    const uint32_t bs0 = (uint32_t)__cvta_generic_to_shared(BsB + b_k * G_BS + b_n4);
    const uint32_t bs1 = (uint32_t)__cvta_generic_to_shared(BsB + (b_k + 8) * G_BS + b_n4);

    const int niter = K / 16;

    auto issue = [&](int it) {
        const int stage = it % GSTAGES;
        const uint32_t ao = stage * (G_ASZ * 4);
        const uint32_t bo = stage * (G_BSZ * 4);
        const size_t gk = (size_t)it * 16;
        cpasync16(as0 + ao, agp0 + gk);
        cpasync16(as1 + ao, agp1 + gk);
        cpasync16(bs0 + bo, bgp0 + gk * ldb);
        cpasync16(bs1 + bo, bgp1 + gk * ldb);
        cp_commit();
    };

    float acc[2][8][4];
    #pragma unroll
    for (int mi = 0; mi < 2; mi++)
        #pragma unroll
        for (int ni = 0; ni < 8; ni++)
            #pragma unroll
            for (int q = 0; q < 4; q++) acc[mi][ni][q] = 0.f;

    issue(0);
    issue(1);

    for (int it = 0; it < niter; ++it) {
        if (it + 1 < niter) asm volatile("cp.async.wait_group 1;");
        else                asm volatile("cp.async.wait_group 0;");
        __syncthreads();
        if (it + 2 < niter) issue(it + 2);

        const int stage = it % GSTAGES;
        const float* As = AsB + stage * G_ASZ;
        const float* Bs = BsB + stage * G_BSZ;

        #pragma unroll
        for (int ks = 0; ks < 2; ks++) {
            const int k = ks * 8;
            uint32_t afr[2][4];
            #pragma unroll
            for (int mi = 0; mi < 2; mi++) {
                int rbse = wm * 32 + mi * 16;
                afr[mi][0] = __float_as_uint(As[(rbse + gid)     * G_AS + k + tig]);
                afr[mi][1] = __float_as_uint(As[(rbse + gid + 8) * G_AS + k + tig]);
                afr[mi][2] = __float_as_uint(As[(rbse + gid)     * G_AS + k + tig + 4]);
                afr[mi][3] = __float_as_uint(As[(rbse + gid + 8) * G_AS + k + tig + 4]);
            }
            uint32_t bfr[8][2];
            #pragma unroll
            for (int ni = 0; ni < 8; ni++) {
                int col = wn * 64 + ni * 8 + gid;
                bfr[ni][0] = __float_as_uint(Bs[(k + tig)     * G_BS + col]);
                bfr[ni][1] = __float_as_uint(Bs[(k + tig + 4) * G_BS + col]);
            }
            #pragma unroll
            for (int mi = 0; mi < 2; mi++)
                #pragma unroll
                for (int ni = 0; ni < 8; ni++)
                    mma_tf32(acc[mi][ni], afr[mi][0], afr[mi][1], afr[mi][2], afr[mi][3],
                             bfr[ni][0], bfr[ni][1]);
        }
        __syncthreads();
    }

    // ---- epilogue ----
    #pragma unroll
    for (int mi = 0; mi < 2; mi++) {
        #pragma unroll
        for (int ni = 0; ni < 8; ni++) {
            int row = m0 + wm * 32 + mi * 16 + gid;
            int col = n0 + wn * 64 + ni * 8 + tig * 2;
            float v0 = acc[mi][ni][0];
            float v1 = acc[mi][ni][1];
            float v2 = acc[mi][ni][2];
            float v3 = acc[mi][ni][3];
            if (bias) {
                float bb0 = bias[col], bb1 = bias[col + 1];
                v0 += bb0; v1 += bb1; v2 += bb0; v3 += bb1;
            }
            if (GELU) {
                v0 = 0.5f * v0 * (1.f + erff(v0 * 0.70710678118654752f));
                v1 = 0.5f * v1 * (1.f + erff(v1 * 0.70710678118654752f));
                v2 = 0.5f * v2 * (1.f + erff(v2 * 0.70710678118654752f));
                v3 = 0.5f * v3 * (1.f + erff(v3 * 0.70710678118654752f));
            }
            if (res) {
                const float2 r0 = *reinterpret_cast<const float2*>(res + (size_t)row * ldc + col);
                const float2 r1 = *reinterpret_cast<const float2*>(res + (size_t)(row + 8) * ldc + col);
                v0 += r0.x; v1 += r0.y; v2 += r1.x; v3 += r1.y;
            }
            *reinterpret_cast<float2*>(C + (size_t)row * ldc + col)       = make_float2(v0, v1);
            *reinterpret_cast<float2*>(C + (size_t)(row + 8) * ldc + col) = make_float2(v2, v3);
        }
    }
}

// ---------------- launch ---------------------------------------------------------
extern "C" void kernel_launch(void* const* d_in, const int* in_sizes, int n_in,
                              void* d_out, int out_size) {
    const float* x      = (const float*)d_in[0];
    const float* g1     = (const float*)d_in[1];
    const float* b1     = (const float*)d_in[2];
    const float* g2     = (const float*)d_in[3];
    const float* b2     = (const float*)d_in[4];
    const float* w_qkv  = (const float*)d_in[5];
    const float* w_proj = (const float*)d_in[6];
    const float* b_proj = (const float*)d_in[7];
    const float* w_fc1  = (const float*)d_in[8];
    const float* b_fc1  = (const float*)d_in[9];
    const float* w_fc2  = (const float*)d_in[10];
    const float* b_fc2  = (const float*)d_in[11];
    float* out = (float*)d_out;

    float *p_h, *p_qkv, *p_attn, *p_x2, *p_h2, *p_hid;
    cudaGetSymbolAddress((void**)&p_h,    g_h);
    cudaGetSymbolAddress((void**)&p_qkv,  g_qkv);
    cudaGetSymbolAddress((void**)&p_attn, g_attn);
    cudaGetSymbolAddress((void**)&p_x2,   g_x2);
    cudaGetSymbolAddress((void**)&p_h2,   g_h2);
    cudaGetSymbolAddress((void**)&p_hid,  g_hid);

    const int FLASH_SMEM = (BQ*QS_ST + BKV*KS_ST + BKV*VS_ST + 8*16*PS_ST) * 4;
    static bool attr_set = false;
    if (!attr_set) {
        cudaFuncSetAttribute(flash_kernel,
                             cudaFuncAttributeMaxDynamicSharedMemorySize, FLASH_SMEM);
        cudaFuncSetAttribute(gemm_cp<false>,
                             cudaFuncAttributeMaxDynamicSharedMemorySize, GEMM_SMEM);
        cudaFuncSetAttribute(gemm_cp<true>,
                             cudaFuncAttributeMaxDynamicSharedMemorySize, GEMM_SMEM);
        attr_set = true;
    }

    // 1) LN1
    ln_kernel<<<TOKENS, 256>>>(x, g1, b1, p_h);

    // 2) qkv = h @ w_qkv
    gemm_cp<false><<<dim3(3*EMBED/128, TOKENS/128), 256, GEMM_SMEM>>>(
        p_h, w_qkv, p_qkv, EMBED, EMBED, 3*EMBED, 3*EMBED, nullptr, nullptr);

    // 3-5) fused attention
    flash_kernel<<<dim3(SEQ/BQ, BHT), 256, FLASH_SMEM>>>(p_qkv, p_attn);

    // 6) x2 = attn @ w_proj + b_proj + x
    gemm_cp<false><<<dim3(EMBED/128, TOKENS/128), 256, GEMM_SMEM>>>(
        p_attn, w_proj, p_x2, EMBED, EMBED, EMBED, EMBED, b_proj, x);

    // 7) LN2
    ln_kernel<<<TOKENS, 256>>>(p_x2, g2, b2, p_h2);

    // 8) hid = gelu(h2 @ w_fc1 + b_fc1)
    gemm_cp<true><<<dim3(HIDDEN/128, TOKENS/128), 256, GEMM_SMEM>>>(
        p_h2, w_fc1, p_hid, EMBED, EMBED, HIDDEN, HIDDEN, b_fc1, nullptr);

    // 9) out = hid @ w_fc2 + b_fc2 + x2
    gemm_cp<false><<<dim3(EMBED/128, TOKENS/128), 256, GEMM_SMEM>>>(
        p_hid, w_fc2, out, HIDDEN, HIDDEN, EMBED, EMBED, b_fc2, p_x2);
}

// round 5
// speedup vs baseline: 3.7032x; 1.0877x over previous
#include <cuda_runtime.h>
#include <math.h>
#include <stdint.h>

#define EMBED   768
#define HEADS   12
#define HDIM    64
#define HIDDEN  3072
#define BATCHSZ 8
#define SEQ     1024
#define TOKENS  (BATCHSZ*SEQ)     // 8192
#define BHT     (BATCHSZ*HEADS)   // 96

// ---------------- scratch ----------------------------------------------------
__device__ float g_h   [(size_t)TOKENS*EMBED];
__device__ float g_qkv [(size_t)TOKENS*3*EMBED];
__device__ float g_attn[(size_t)TOKENS*EMBED];
__device__ float g_x2  [(size_t)TOKENS*EMBED];
__device__ float g_h2  [(size_t)TOKENS*EMBED];
__device__ float g_hid [(size_t)TOKENS*HIDDEN];

// ---------------- LayerNorm ---------------------------------------------------
__global__ void ln_kernel(const float* __restrict__ x,
                          const float* __restrict__ g,
                          const float* __restrict__ b,
                          float* __restrict__ out) {
    int row = blockIdx.x;
    const float* xr = x + (size_t)row * EMBED;
    float s = 0.f, s2 = 0.f;
    for (int i = threadIdx.x; i < EMBED; i += blockDim.x) {
        float v = xr[i]; s += v; s2 += v * v;
    }
    __shared__ float red[64];
    int wid = threadIdx.x >> 5, lid = threadIdx.x & 31;
    #pragma unroll
    for (int o = 16; o; o >>= 1) {
        s  += __shfl_down_sync(0xffffffffu, s,  o);
        s2 += __shfl_down_sync(0xffffffffu, s2, o);
    }
    if (lid == 0) { red[wid] = s; red[wid + 32] = s2; }
    __syncthreads();
    if (wid == 0) {
        int nw = blockDim.x >> 5;
        s  = (lid < nw) ? red[lid]      : 0.f;
        s2 = (lid < nw) ? red[lid + 32] : 0.f;
        #pragma unroll
        for (int o = 16; o; o >>= 1) {
            s  += __shfl_down_sync(0xffffffffu, s,  o);
            s2 += __shfl_down_sync(0xffffffffu, s2, o);
        }
        if (lid == 0) { red[0] = s; red[1] = s2; }
    }
    __syncthreads();
    float mu  = red[0] * (1.f / EMBED);
    float var = red[1] * (1.f / EMBED) - mu * mu;
    float rstd = rsqrtf(var + 1e-5f);
    float* o = out + (size_t)row * EMBED;
    for (int i = threadIdx.x; i < EMBED; i += blockDim.x)
        o[i] = (xr[i] - mu) * rstd * g[i] + b[i];
}

// ---------------- mma helper -----------------------------------------------------
__device__ __forceinline__ void mma_tf32(float c[4],
                                         uint32_t a0, uint32_t a1, uint32_t a2, uint32_t a3,
                                         uint32_t b0, uint32_t b1) {
    asm volatile(
        "mma.sync.aligned.m16n8k8.row.col.f32.tf32.tf32.f32 "
        "{%0,%1,%2,%3}, {%4,%5,%6,%7}, {%8,%9}, {%0,%1,%2,%3};"
        : "+f"(c[0]), "+f"(c[1]), "+f"(c[2]), "+f"(c[3])
        : "r"(a0), "r"(a1), "r"(a2), "r"(a3), "r"(b0), "r"(b1));
}

__device__ __forceinline__ void cpasync16(uint32_t s, const void* g) {
    asm volatile("cp.async.cg.shared.global [%0], [%1], 16;" :: "r"(s), "l"(g));
}
__device__ __forceinline__ void cp_commit() {
    asm volatile("cp.async.commit_group;");
}

// ---------------- fused flash attention ------------------------------------------
#define BQ  128
#define BKV 128
#define QS_ST 68
#define KS_ST 68
#define VS_ST 72
#define PS_ST 132

__global__ void __launch_bounds__(256)
flash_kernel(const float* __restrict__ qkv, float* __restrict__ attn) {
    extern __shared__ float sm[];
    float* Qs = sm;
    float* Ks = Qs + BQ * QS_ST;
    float* Vs = Ks + BKV * KS_ST;
    float* Ps = Vs + BKV * VS_ST;

    const int tid  = threadIdx.x;
    const int warp = tid >> 5, lane = tid & 31;
    const int gid  = lane >> 2, tig = lane & 3;
    const int bh = blockIdx.y;
    const int b  = bh / HEADS, h = bh % HEADS;
    const int q0 = blockIdx.x * BQ;
    const int wrow = warp * 16;
    float* Pw = Ps + warp * 16 * PS_ST;

    const float* qbase = qkv + ((size_t)b * SEQ) * 3 * EMBED + h * HDIM;
    const float* kbase = qbase + EMBED;
    const float* vbase = qbase + 2 * EMBED;

    #pragma unroll
    for (int i = 0; i < 8; i++) {
        int s = tid + i * 256;
        int r = s >> 4, c = (s & 15) * 4;
        float4 v = *reinterpret_cast<const float4*>(qbase + (size_t)(q0 + r) * 3 * EMBED + c);
        *reinterpret_cast<float4*>(&Qs[r * QS_ST + c]) =
            make_float4(v.x * 0.125f, v.y * 0.125f, v.z * 0.125f, v.w * 0.125f);
    }

    float m0 = -1e30f, m1 = -1e30f, l0 = 0.f, l1 = 0.f;
    float oacc[8][4];
    #pragma unroll
    for (int ni = 0; ni < 8; ni++)
        #pragma unroll
        for (int q = 0; q < 4; q++) oacc[ni][q] = 0.f;

    for (int t = 0; t < SEQ / BKV; t++) {
        __syncthreads();
        #pragma unroll
        for (int i = 0; i < 8; i++) {
            int s = tid + i * 256;
            int r = s >> 4, c = (s & 15) * 4;
            size_t row_off = (size_t)(t * BKV + r) * 3 * EMBED + c;
            *reinterpret_cast<float4*>(&Ks[r * KS_ST + c]) =
                *reinterpret_cast<const float4*>(kbase + row_off);
            *reinterpret_cast<float4*>(&Vs[r * VS_ST + c]) =
                *reinterpret_cast<const float4*>(vbase + row_off);
        }
        __syncthreads();

        float sacc[16][4];
        #pragma unroll
        for (int ni = 0; ni < 16; ni++)
            #pragma unroll
            for (int q = 0; q < 4; q++) sacc[ni][q] = 0.f;

        #pragma unroll
        for (int ks = 0; ks < 8; ks++) {
            const int k = ks * 8;
            uint32_t a0 = __float_as_uint(Qs[(wrow + gid)     * QS_ST + k + tig]);
            uint32_t a1 = __float_as_uint(Qs[(wrow + gid + 8) * QS_ST + k + tig]);
            uint32_t a2 = __float_as_uint(Qs[(wrow + gid)     * QS_ST + k + tig + 4]);
            uint32_t a3 = __float_as_uint(Qs[(wrow + gid + 8) * QS_ST + k + tig + 4]);
            #pragma unroll
            for (int ni = 0; ni < 16; ni++) {
                uint32_t b0 = __float_as_uint(Ks[(ni * 8 + gid) * KS_ST + k + tig]);
                uint32_t b1 = __float_as_uint(Ks[(ni * 8 + gid) * KS_ST + k + tig + 4]);
                mma_tf32(sacc[ni], a0, a1, a2, a3, b0, b1);
            }
        }

        float rmax0 = -1e30f, rmax1 = -1e30f;
        #pragma unroll
        for (int ni = 0; ni < 16; ni++) {
            rmax0 = fmaxf(rmax0, fmaxf(sacc[ni][0], sacc[ni][1]));
            rmax1 = fmaxf(rmax1, fmaxf(sacc[ni][2], sacc[ni][3]));
        }
        #pragma unroll
        for (int o = 1; o <= 2; o <<= 1) {
            rmax0 = fmaxf(rmax0, __shfl_xor_sync(0xffffffffu, rmax0, o));
            rmax1 = fmaxf(rmax1, __shfl_xor_sync(0xffffffffu, rmax1, o));
        }
        float mn0 = fmaxf(m0, rmax0);
        float mn1 = fmaxf(m1, rmax1);
        float sf0 = __expf(m0 - mn0);
        float sf1 = __expf(m1 - mn1);

        float rs0 = 0.f, rs1 = 0.f;
        #pragma unroll
        for (int ni = 0; ni < 16; ni++) {
            float p0 = __expf(sacc[ni][0] - mn0);
            float p1 = __expf(sacc[ni][1] - mn0);
            float p2 = __expf(sacc[ni][2] - mn1);
            float p3 = __expf(sacc[ni][3] - mn1);
            rs0 += p0 + p1;
            rs1 += p2 + p3;
            int cc = ni * 8 + tig * 2;
            *reinterpret_cast<float2*>(&Pw[gid * PS_ST + cc])       = make_float2(p0, p1);
            *reinterpret_cast<float2*>(&Pw[(gid + 8) * PS_ST + cc]) = make_float2(p2, p3);
        }
        #pragma unroll
        for (int o = 1; o <= 2; o <<= 1) {
            rs0 += __shfl_xor_sync(0xffffffffu, rs0, o);
            rs1 += __shfl_xor_sync(0xffffffffu, rs1, o);
        }
        l0 = l0 * sf0 + rs0;
        l1 = l1 * sf1 + rs1;
        m0 = mn0;
        m1 = mn1;

        #pragma unroll
        for (int ni = 0; ni < 8; ni++) {
            oacc[ni][0] *= sf0; oacc[ni][1] *= sf0;
            oacc[ni][2] *= sf1; oacc[ni][3] *= sf1;
        }
        __syncwarp();

        #pragma unroll
        for (int ks = 0; ks < 16; ks++) {
            const int k = ks * 8;
            uint32_t a0 = __float_as_uint(Pw[gid * PS_ST + k + tig]);
            uint32_t a1 = __float_as_uint(Pw[(gid + 8) * PS_ST + k + tig]);
            uint32_t a2 = __float_as_uint(Pw[gid * PS_ST + k + tig + 4]);
            uint32_t a3 = __float_as_uint(Pw[(gid + 8) * PS_ST + k + tig + 4]);
            #pragma unroll
            for (int ni = 0; ni < 8; ni++) {
                uint32_t b0 = __float_as_uint(Vs[(k + tig)     * VS_ST + ni * 8 + gid]);
                uint32_t b1 = __float_as_uint(Vs[(k + tig + 4) * VS_ST + ni * 8 + gid]);
                mma_tf32(oacc[ni], a0, a1, a2, a3, b0, b1);
            }
        }
    }

    float inv0 = 1.f / l0;
    float inv1 = 1.f / l1;
    const int tok0 = b * SEQ + q0 + wrow;
    #pragma unroll
    for (int ni = 0; ni < 8; ni++) {
        int col = h * HDIM + ni * 8 + tig * 2;
        *reinterpret_cast<float2*>(attn + (size_t)(tok0 + gid) * EMBED + col) =
            make_float2(oacc[ni][0] * inv0, oacc[ni][1] * inv0);
        *reinterpret_cast<float2*>(attn + (size_t)(tok0 + gid + 8) * EMBED + col) =
            make_float2(oacc[ni][2] * inv1, oacc[ni][3] * inv1);
    }
}

// ---------------- cp.async pipelined tensor-core GEMM (NN, BK=32) -----------------
#define GSTAGES 3
#define GBK  32
#define G_AS 36             // A smem row stride (floats), banks: 4r+t all distinct
#define G_BS 136            // B smem row stride (floats), banks: 8t+g all distinct
#define G_ASZ (128 * G_AS)  // floats per A stage (4608)
#define G_BSZ (GBK * G_BS)  // floats per B stage (4352)
#define GEMM_SMEM (GSTAGES * (G_ASZ + G_BSZ) * 4)   // 107520 B

template<bool GELU>
__global__ void __launch_bounds__(256, 2)
gemm_cp(const float* __restrict__ A, const float* __restrict__ B,
        float* __restrict__ C,
        int K, int lda, int ldb, int ldc,
        const float* __restrict__ bias,
        const float* __restrict__ res) {
    extern __shared__ float smp[];
    float* AsB = smp;
    float* BsB = smp + GSTAGES * G_ASZ;

    const int tid = threadIdx.x;
    const int warp = tid >> 5, lane = tid & 31;
    const int gid = lane >> 2, tig = lane & 3;
    const int wm = warp >> 1, wn = warp & 1;

    const int m0 = blockIdx.y * 128;
    const int n0 = blockIdx.x * 128;

    // copy coordinates: A 128 rows x 32 k (8 chunks/row, 1024 chunks, 4/thread)
    //                   B 32 k x 128 n (32 chunks/k-row, 1024 chunks, 4/thread)
    const int a_m  = tid >> 1, a_kc = (tid & 1) * 16;   // +128 rows per pass pair... (see below)
    const int b_k  = tid >> 5, b_n4 = (tid & 31) * 4;

    // A: thread handles rows a_m (chunks at k-offsets a_kc, a_kc+4) and a_m+... :
    // simpler mapping: chunk c = tid + pass*256; row = c>>3; kc = (c&7)*4
    const uint32_t asb = (uint32_t)__cvta_generic_to_shared(AsB);
    const uint32_t bsb = (uint32_t)__cvta_generic_to_shared(BsB);

    const int niter = K / GBK;

    auto issue = [&](int it) {
        const int stage = it % GSTAGES;
        const uint32_t ao = asb + stage * (G_ASZ * 4);
        const uint32_t bo = bsb + stage * (G_BSZ * 4);
        const int k0 = it * GBK;
        #pragma unroll
        for (int p = 0; p < 4; p++) {
            int c = tid + p * 256;
            int row = c >> 3, kc = (c & 7) * 4;
            cpasync16(ao + (row * G_AS + kc) * 4,
                      A + (size_t)(m0 + row) * lda + k0 + kc);
        }
        #pragma unroll
        for (int p = 0; p < 4; p++) {
            int c = tid + p * 256;
            int k = c >> 5, n4 = (c & 31) * 4;
            cpasync16(bo + (k * G_BS + n4) * 4,
                      B + (size_t)(k0 + k) * ldb + n0 + n4);
        }
        cp_commit();
    };

    float acc[2][8][4];
    #pragma unroll
    for (int mi = 0; mi < 2; mi++)
        #pragma unroll
        for (int ni = 0; ni < 8; ni++)
            #pragma unroll
            for (int q = 0; q < 4; q++) acc[mi][ni][q] = 0.f;

    issue(0);
    issue(1);

    for (int it = 0; it < niter; ++it) {
        if (it + 1 < niter) asm volatile("cp.async.wait_group 1;");
        else                asm volatile("cp.async.wait_group 0;");
        __syncthreads();
        if (it + 2 < niter) issue(it + 2);

        const int stage = it % GSTAGES;
        const float* As = AsB + stage * G_ASZ;
        const float* Bs = BsB + stage * G_BSZ;

        #pragma unroll
        for (int ks = 0; ks < GBK / 8; ks++) {
            const int k = ks * 8;
            uint32_t afr[2][4];
            #pragma unroll
            for (int mi = 0; mi < 2; mi++) {
                int rbse = wm * 32 + mi * 16;
                afr[mi][0] = __float_as_uint(As[(rbse + gid)     * G_AS + k + tig]);
                afr[mi][1] = __float_as_uint(As[(rbse + gid + 8) * G_AS + k + tig]);
                afr[mi][2] = __float_as_uint(As[(rbse + gid)     * G_AS + k + tig + 4]);
                afr[mi][3] = __float_as_uint(As[(rbse + gid + 8) * G_AS + k + tig + 4]);
            }
            uint32_t bfr[8][2];
            #pragma unroll
            for (int ni = 0; ni < 8; ni++) {
                int col = wn * 64 + ni * 8 + gid;
                bfr[ni][0] = __float_as_uint(Bs[(k + tig)     * G_BS + col]);
                bfr[ni][1] = __float_as_uint(Bs[(k + tig + 4) * G_BS + col]);
            }
            #pragma unroll
            for (int mi = 0; mi < 2; mi++)
                #pragma unroll
                for (int ni = 0; ni < 8; ni++)
                    mma_tf32(acc[mi][ni], afr[mi][0], afr[mi][1], afr[mi][2], afr[mi][3],
                             bfr[ni][0], bfr[ni][1]);
        }
        // single sync per iter: top-sync of it+1 guarantees these reads are done
        // before any warp issues into stage (it)%GSTAGES again (3 iters later).
    }

    // ---- epilogue ----
    #pragma unroll
    for (int mi = 0; mi < 2; mi++) {
        #pragma unroll
        for (int ni = 0; ni < 8; ni++) {
            int row = m0 + wm * 32 + mi * 16 + gid;
            int col = n0 + wn * 64 + ni * 8 + tig * 2;
            float v0 = acc[mi][ni][0];
            float v1 = acc[mi][ni][1];
            float v2 = acc[mi][ni][2];
            float v3 = acc[mi][ni][3];
            if (bias) {
                float bb0 = bias[col], bb1 = bias[col + 1];
                v0 += bb0; v1 += bb1; v2 += bb0; v3 += bb1;
            }
            if (GELU) {
                v0 = 0.5f * v0 * (1.f + erff(v0 * 0.70710678118654752f));
                v1 = 0.5f * v1 * (1.f + erff(v1 * 0.70710678118654752f));
                v2 = 0.5f * v2 * (1.f + erff(v2 * 0.70710678118654752f));
                v3 = 0.5f * v3 * (1.f + erff(v3 * 0.70710678118654752f));
            }
            if (res) {
                const float2 r0 = *reinterpret_cast<const float2*>(res + (size_t)row * ldc + col);
                const float2 r1 = *reinterpret_cast<const float2*>(res + (size_t)(row + 8) * ldc + col);
                v0 += r0.x; v1 += r0.y; v2 += r1.x; v3 += r1.y;
            }
            *reinterpret_cast<float2*>(C + (size_t)row * ldc + col)       = make_float2(v0, v1);
            *reinterpret_cast<float2*>(C + (size_t)(row + 8) * ldc + col) = make_float2(v2, v3);
        }
    }
}

// ---------------- launch ---------------------------------------------------------
extern "C" void kernel_launch(void* const* d_in, const int* in_sizes, int n_in,
                              void* d_out, int out_size) {
    const float* x      = (const float*)d_in[0];
    const float* g1     = (const float*)d_in[1];
    const float* b1     = (const float*)d_in[2];
    const float* g2     = (const float*)d_in[3];
    const float* b2     = (const float*)d_in[4];
    const float* w_qkv  = (const float*)d_in[5];
    const float* w_proj = (const float*)d_in[6];
    const float* b_proj = (const float*)d_in[7];
    const float* w_fc1  = (const float*)d_in[8];
    const float* b_fc1  = (const float*)d_in[9];
    const float* w_fc2  = (const float*)d_in[10];
    const float* b_fc2  = (const float*)d_in[11];
    float* out = (float*)d_out;

    float *p_h, *p_qkv, *p_attn, *p_x2, *p_h2, *p_hid;
    cudaGetSymbolAddress((void**)&p_h,    g_h);
    cudaGetSymbolAddress((void**)&p_qkv,  g_qkv);
    cudaGetSymbolAddress((void**)&p_attn, g_attn);
    cudaGetSymbolAddress((void**)&p_x2,   g_x2);
    cudaGetSymbolAddress((void**)&p_h2,   g_h2);
    cudaGetSymbolAddress((void**)&p_hid,  g_hid);

    const int FLASH_SMEM = (BQ*QS_ST + BKV*KS_ST + BKV*VS_ST + 8*16*PS_ST) * 4;
    static bool attr_set = false;
    if (!attr_set) {
        cudaFuncSetAttribute(flash_kernel,
                             cudaFuncAttributeMaxDynamicSharedMemorySize, FLASH_SMEM);
        cudaFuncSetAttribute(gemm_cp<false>,
                             cudaFuncAttributeMaxDynamicSharedMemorySize, GEMM_SMEM);
        cudaFuncSetAttribute(gemm_cp<true>,
                             cudaFuncAttributeMaxDynamicSharedMemorySize, GEMM_SMEM);
        attr_set = true;
    }

    // 1) LN1
    ln_kernel<<<TOKENS, 256>>>(x, g1, b1, p_h);

    // 2) qkv = h @ w_qkv
    gemm_cp<false><<<dim3(3*EMBED/128, TOKENS/128), 256, GEMM_SMEM>>>(
        p_h, w_qkv, p_qkv, EMBED, EMBED, 3*EMBED, 3*EMBED, nullptr, nullptr);

    // 3-5) fused attention
    flash_kernel<<<dim3(SEQ/BQ, BHT), 256, FLASH_SMEM>>>(p_qkv, p_attn);

    // 6) x2 = attn @ w_proj + b_proj + x
    gemm_cp<false><<<dim3(EMBED/128, TOKENS/128), 256, GEMM_SMEM>>>(
        p_attn, w_proj, p_x2, EMBED, EMBED, EMBED, EMBED, b_proj, x);

    // 7) LN2
    ln_kernel<<<TOKENS, 256>>>(p_x2, g2, b2, p_h2);

    // 8) hid = gelu(h2 @ w_fc1 + b_fc1)
    gemm_cp<true><<<dim3(HIDDEN/128, TOKENS/128), 256, GEMM_SMEM>>>(
        p_h2, w_fc1, p_hid, EMBED, EMBED, HIDDEN, HIDDEN, b_fc1, nullptr);

    // 9) out = hid @ w_fc2 + b_fc2 + x2
    gemm_cp<false><<<dim3(EMBED/128, TOKENS/128), 256, GEMM_SMEM>>>(
        p_hid, w_fc2, out, HIDDEN, HIDDEN, EMBED, EMBED, b_fc2, p_x2);
}

// round 7
// speedup vs baseline: 4.3489x; 1.1744x over previous
#include <cuda_runtime.h>
#include <math.h>
#include <stdint.h>

#define EMBED   768
#define HEADS   12
#define HDIM    64
#define HIDDEN  3072
#define BATCHSZ 8
#define SEQ     1024
#define TOKENS  (BATCHSZ*SEQ)     // 8192
#define BHT     (BATCHSZ*HEADS)   // 96

// ---------------- scratch ----------------------------------------------------
__device__ float g_h   [(size_t)TOKENS*EMBED];
__device__ float g_qkv [(size_t)TOKENS*3*EMBED];
__device__ float g_attn[(size_t)TOKENS*EMBED];
__device__ float g_x2  [(size_t)TOKENS*EMBED];
__device__ float g_h2  [(size_t)TOKENS*EMBED];
__device__ float g_hid [(size_t)TOKENS*HIDDEN];

// ---------------- LayerNorm ---------------------------------------------------
__global__ void ln_kernel(const float* __restrict__ x,
                          const float* __restrict__ g,
                          const float* __restrict__ b,
                          float* __restrict__ out) {
    int row = blockIdx.x;
    const float* xr = x + (size_t)row * EMBED;
    float s = 0.f, s2 = 0.f;
    for (int i = threadIdx.x; i < EMBED; i += blockDim.x) {
        float v = xr[i]; s += v; s2 += v * v;
    }
    __shared__ float red[64];
    int wid = threadIdx.x >> 5, lid = threadIdx.x & 31;
    #pragma unroll
    for (int o = 16; o; o >>= 1) {
        s  += __shfl_down_sync(0xffffffffu, s,  o);
        s2 += __shfl_down_sync(0xffffffffu, s2, o);
    }
    if (lid == 0) { red[wid] = s; red[wid + 32] = s2; }
    __syncthreads();
    if (wid == 0) {
        int nw = blockDim.x >> 5;
        s  = (lid < nw) ? red[lid]      : 0.f;
        s2 = (lid < nw) ? red[lid + 32] : 0.f;
        #pragma unroll
        for (int o = 16; o; o >>= 1) {
            s  += __shfl_down_sync(0xffffffffu, s,  o);
            s2 += __shfl_down_sync(0xffffffffu, s2, o);
        }
        if (lid == 0) { red[0] = s; red[1] = s2; }
    }
    __syncthreads();
    float mu  = red[0] * (1.f / EMBED);
    float var = red[1] * (1.f / EMBED) - mu * mu;
    float rstd = rsqrtf(var + 1e-5f);
    float* o = out + (size_t)row * EMBED;
    for (int i = threadIdx.x; i < EMBED; i += blockDim.x)
        o[i] = (xr[i] - mu) * rstd * g[i] + b[i];
}

// ---------------- mma helper -----------------------------------------------------
__device__ __forceinline__ void mma_tf32(float c[4],
                                         uint32_t a0, uint32_t a1, uint32_t a2, uint32_t a3,
                                         uint32_t b0, uint32_t b1) {
    asm volatile(
        "mma.sync.aligned.m16n8k8.row.col.f32.tf32.tf32.f32 "
        "{%0,%1,%2,%3}, {%4,%5,%6,%7}, {%8,%9}, {%0,%1,%2,%3};"
        : "+f"(c[0]), "+f"(c[1]), "+f"(c[2]), "+f"(c[3])
        : "r"(a0), "r"(a1), "r"(a2), "r"(a3), "r"(b0), "r"(b1));
}

__device__ __forceinline__ void cpasync16(uint32_t s, const void* g) {
    asm volatile("cp.async.cg.shared.global [%0], [%1], 16;" :: "r"(s), "l"(g));
}
__device__ __forceinline__ void cp_commit() {
    asm volatile("cp.async.commit_group;");
}

// ---------------- fused flash attention (cp.async double-buffered KV) -------------
// Per CTA: 128 Q rows of one (b,h). Q fragments live in registers (loaded once).
// KV tiles double-buffered via cp.async: load(t+1) overlaps compute(t).
#define BQ  128
#define BKV 128
#define KD_ST 68
#define VD_ST 72
#define PS_ST 132
#define PS_FLOATS   (8 * 16 * PS_ST)                 // 16896
#define KVS_FLOATS  (BKV * (KD_ST + VD_ST))          // 17920 per stage
#define FLASH_SMEM  ((PS_FLOATS + 2 * KVS_FLOATS) * 4)   // 210944 B

__global__ void __launch_bounds__(256)
flash_kernel(const float* __restrict__ qkv, float* __restrict__ attn) {
    extern __shared__ float sm[];
    float* Ps  = sm;                                  // also Q staging initially
    float* KV0 = sm + PS_FLOATS;
    float* KV1 = KV0 + KVS_FLOATS;

    const int tid  = threadIdx.x;
    const int warp = tid >> 5, lane = tid & 31;
    const int gid  = lane >> 2, tig = lane & 3;
    const int bh = blockIdx.y;
    const int b  = bh / HEADS, h = bh % HEADS;
    const int q0 = blockIdx.x * BQ;
    const int wrow = warp * 16;
    float* Pw = Ps + warp * 16 * PS_ST;

    const float* qbase = qkv + ((size_t)b * SEQ) * 3 * EMBED + h * HDIM;
    const float* kbase = qbase + EMBED;
    const float* vbase = qbase + 2 * EMBED;

    // ---- stage Q (scaled) into Ps, then lift fragments to registers ----
    #pragma unroll
    for (int i = 0; i < 8; i++) {
        int s = tid + i * 256;
        int r = s >> 4, c = (s & 15) * 4;
        float4 v = *reinterpret_cast<const float4*>(qbase + (size_t)(q0 + r) * 3 * EMBED + c);
        *reinterpret_cast<float4*>(&Ps[r * PS_ST + c]) =
            make_float4(v.x * 0.125f, v.y * 0.125f, v.z * 0.125f, v.w * 0.125f);
    }
    __syncthreads();
    uint32_t qf[8][4];
    #pragma unroll
    for (int ks = 0; ks < 8; ks++) {
        const int k = ks * 8;
        qf[ks][0] = __float_as_uint(Ps[(wrow + gid)     * PS_ST + k + tig]);
        qf[ks][1] = __float_as_uint(Ps[(wrow + gid + 8) * PS_ST + k + tig]);
        qf[ks][2] = __float_as_uint(Ps[(wrow + gid)     * PS_ST + k + tig + 4]);
        qf[ks][3] = __float_as_uint(Ps[(wrow + gid + 8) * PS_ST + k + tig + 4]);
    }
    __syncthreads();   // Ps free for P use

    // ---- KV stage loader ----
    const uint32_t kv0s = (uint32_t)__cvta_generic_to_shared(KV0);
    const uint32_t kv1s = (uint32_t)__cvta_generic_to_shared(KV1);
    auto issue_kv = [&](int t) {
        const uint32_t base = (t & 1) ? kv1s : kv0s;
        const uint32_t vofs = BKV * KD_ST * 4;
        #pragma unroll
        for (int p = 0; p < 8; p++) {
            int c = tid + p * 256;
            int r = c >> 4, c16 = c & 15;
            size_t gro = (size_t)(t * BKV + r) * 3 * EMBED + c16 * 4;
            cpasync16(base + (r * KD_ST + c16 * 4) * 4,        kbase + gro);
            cpasync16(base + vofs + (r * VD_ST + c16 * 4) * 4, vbase + gro);
        }
        cp_commit();
    };

    float m0 = -1e30f, m1 = -1e30f, l0 = 0.f, l1 = 0.f;
    float oacc[8][4];
    #pragma unroll
    for (int ni = 0; ni < 8; ni++)
        #pragma unroll
        for (int q = 0; q < 4; q++) oacc[ni][q] = 0.f;

    issue_kv(0);

    for (int t = 0; t < SEQ / BKV; t++) {
        if (t + 1 < SEQ / BKV) {
            issue_kv(t + 1);                     // buffer (t+1)&1 free since compute(t-1) barrier
            asm volatile("cp.async.wait_group 1;");
        } else {
            asm volatile("cp.async.wait_group 0;");
        }
        __syncthreads();                          // stage t visible to all warps

        const float* Ks = (t & 1) ? KV1 : KV0;
        const float* Vs = Ks + BKV * KD_ST;

        // ---- S = Q @ K^T ----
        float sacc[16][4];
        #pragma unroll
        for (int ni = 0; ni < 16; ni++)
            #pragma unroll
            for (int q = 0; q < 4; q++) sacc[ni][q] = 0.f;

        #pragma unroll
        for (int ks = 0; ks < 8; ks++) {
            const int k = ks * 8;
            #pragma unroll
            for (int ni = 0; ni < 16; ni++) {
                uint32_t b0 = __float_as_uint(Ks[(ni * 8 + gid) * KD_ST + k + tig]);
                uint32_t b1 = __float_as_uint(Ks[(ni * 8 + gid) * KD_ST + k + tig + 4]);
                mma_tf32(sacc[ni], qf[ks][0], qf[ks][1], qf[ks][2], qf[ks][3], b0, b1);
            }
        }

        // ---- online softmax ----
        float rmax0 = -1e30f, rmax1 = -1e30f;
        #pragma unroll
        for (int ni = 0; ni < 16; ni++) {
            rmax0 = fmaxf(rmax0, fmaxf(sacc[ni][0], sacc[ni][1]));
            rmax1 = fmaxf(rmax1, fmaxf(sacc[ni][2], sacc[ni][3]));
        }
        #pragma unroll
        for (int o = 1; o <= 2; o <<= 1) {
            rmax0 = fmaxf(rmax0, __shfl_xor_sync(0xffffffffu, rmax0, o));
            rmax1 = fmaxf(rmax1, __shfl_xor_sync(0xffffffffu, rmax1, o));
        }
        float mn0 = fmaxf(m0, rmax0);
        float mn1 = fmaxf(m1, rmax1);
        float sf0 = __expf(m0 - mn0);
        float sf1 = __expf(m1 - mn1);

        float rs0 = 0.f, rs1 = 0.f;
        #pragma unroll
        for (int ni = 0; ni < 16; ni++) {
            float p0 = __expf(sacc[ni][0] - mn0);
            float p1 = __expf(sacc[ni][1] - mn0);
            float p2 = __expf(sacc[ni][2] - mn1);
            float p3 = __expf(sacc[ni][3] - mn1);
            rs0 += p0 + p1;
            rs1 += p2 + p3;
            int cc = ni * 8 + tig * 2;
            *reinterpret_cast<float2*>(&Pw[gid * PS_ST + cc])       = make_float2(p0, p1);
            *reinterpret_cast<float2*>(&Pw[(gid + 8) * PS_ST + cc]) = make_float2(p2, p3);
        }
        #pragma unroll
        for (int o = 1; o <= 2; o <<= 1) {
            rs0 += __shfl_xor_sync(0xffffffffu, rs0, o);
            rs1 += __shfl_xor_sync(0xffffffffu, rs1, o);
        }
        l0 = l0 * sf0 + rs0;
        l1 = l1 * sf1 + rs1;
        m0 = mn0;
        m1 = mn1;

        #pragma unroll
        for (int ni = 0; ni < 8; ni++) {
            oacc[ni][0] *= sf0; oacc[ni][1] *= sf0;
            oacc[ni][2] *= sf1; oacc[ni][3] *= sf1;
        }
        __syncwarp();

        // ---- O += P @ V ----
        #pragma unroll
        for (int ks = 0; ks < 16; ks++) {
            const int k = ks * 8;
            uint32_t a0 = __float_as_uint(Pw[gid * PS_ST + k + tig]);
            uint32_t a1 = __float_as_uint(Pw[(gid + 8) * PS_ST + k + tig]);
            uint32_t a2 = __float_as_uint(Pw[gid * PS_ST + k + tig + 4]);
            uint32_t a3 = __float_as_uint(Pw[(gid + 8) * PS_ST + k + tig + 4]);
            #pragma unroll
            for (int ni = 0; ni < 8; ni++) {
                uint32_t b0 = __float_as_uint(Vs[(k + tig)     * VD_ST + ni * 8 + gid]);
                uint32_t b1 = __float_as_uint(Vs[(k + tig + 4) * VD_ST + ni * 8 + gid]);
                mma_tf32(oacc[ni], a0, a1, a2, a3, b0, b1);
            }
        }
        __syncthreads();   // all warps done with buffer t before it is refilled (t+2)
    }

    float inv0 = 1.f / l0;
    float inv1 = 1.f / l1;
    const int tok0 = b * SEQ + q0 + wrow;
    #pragma unroll
    for (int ni = 0; ni < 8; ni++) {
        int col = h * HDIM + ni * 8 + tig * 2;
        *reinterpret_cast<float2*>(attn + (size_t)(tok0 + gid) * EMBED + col) =
            make_float2(oacc[ni][0] * inv0, oacc[ni][1] * inv0);
        *reinterpret_cast<float2*>(attn + (size_t)(tok0 + gid + 8) * EMBED + col) =
            make_float2(oacc[ni][2] * inv1, oacc[ni][3] * inv1);
    }
}

// ---------------- cp.async pipelined tensor-core GEMM (NN, BK=32) -----------------
#define GSTAGES 3
#define GBK  32
#define G_AS 36             // A smem row stride (floats)
#define G_BS 136            // B smem row stride (floats)
#define G_ASZ (128 * G_AS)
#define G_BSZ (GBK * G_BS)
#define GEMM_SMEM (GSTAGES * (G_ASZ + G_BSZ) * 4)   // 107520 B

template<bool GELU>
__global__ void __launch_bounds__(256, 2)
gemm_cp(const float* __restrict__ A, const float* __restrict__ B,
        float* __restrict__ C,
        int K, int lda, int ldb, int ldc,
        const float* __restrict__ bias,
        const float* __restrict__ res) {
    extern __shared__ float smp[];
    float* AsB = smp;
    float* BsB = smp + GSTAGES * G_ASZ;

    const int tid = threadIdx.x;
    const int warp = tid >> 5, lane = tid & 31;
    const int gid = lane >> 2, tig = lane & 3;
    const int wm = warp >> 1, wn = warp & 1;

    const int m0 = blockIdx.y * 128;
    const int n0 = blockIdx.x * 128;

    const uint32_t asb = (uint32_t)__cvta_generic_to_shared(AsB);
    const uint32_t bsb = (uint32_t)__cvta_generic_to_shared(BsB);

    const int niter = K / GBK;

    auto issueA = [&](int it) {
        const int stage = it % GSTAGES;
        const uint32_t ao = asb + stage * (G_ASZ * 4);
        const int k0 = it * GBK;
        #pragma unroll
        for (int p = 0; p < 4; p++) {
            int c = tid + p * 256;
            int row = c >> 3, kc = (c & 7) * 4;
            cpasync16(ao + (row * G_AS + kc) * 4,
                      A + (size_t)(m0 + row) * lda + k0 + kc);
        }
    };
    auto issueB = [&](int it) {
        const int stage = it % GSTAGES;
        const uint32_t bo = bsb + stage * (G_BSZ * 4);
        const int k0 = it * GBK;
        #pragma unroll
        for (int p = 0; p < 4; p++) {
            int c = tid + p * 256;
            int k = c >> 5, n4 = (c & 31) * 4;
            cpasync16(bo + (k * G_BS + n4) * 4,
                      B + (size_t)(k0 + k) * ldb + n0 + n4);
        }
    };

    float acc[2][8][4];
    #pragma unroll
    for (int mi = 0; mi < 2; mi++)
        #pragma unroll
        for (int ni = 0; ni < 8; ni++)
            #pragma unroll
            for (int q = 0; q < 4; q++) acc[mi][ni][q] = 0.f;

    issueA(0); issueB(0); cp_commit();
    issueA(1); issueB(1); cp_commit();

    for (int it = 0; it < niter; ++it) {
        if (it + 1 < niter) asm volatile("cp.async.wait_group 1;");
        else                asm volatile("cp.async.wait_group 0;");
        __syncthreads();

        const int stage = it % GSTAGES;
        const float* As = AsB + stage * G_ASZ;
        const float* Bs = BsB + stage * G_BSZ;
        const bool pre = (it + 2 < niter);

        #pragma unroll
        for (int ks = 0; ks < GBK / 8; ks++) {
            const int k = ks * 8;
            uint32_t afr[2][4];
            #pragma unroll
            for (int mi = 0; mi < 2; mi++) {
                int rbse = wm * 32 + mi * 16;
                afr[mi][0] = __float_as_uint(As[(rbse + gid)     * G_AS + k + tig]);
                afr[mi][1] = __float_as_uint(As[(rbse + gid + 8) * G_AS + k + tig]);
                afr[mi][2] = __float_as_uint(As[(rbse + gid)     * G_AS + k + tig + 4]);
                afr[mi][3] = __float_as_uint(As[(rbse + gid + 8) * G_AS + k + tig + 4]);
            }
            uint32_t bfr[8][2];
            #pragma unroll
            for (int ni = 0; ni < 8; ni++) {
                int col = wn * 64 + ni * 8 + gid;
                bfr[ni][0] = __float_as_uint(Bs[(k + tig)     * G_BS + col]);
                bfr[ni][1] = __float_as_uint(Bs[(k + tig + 4) * G_BS + col]);
            }
            #pragma unroll
            for (int mi = 0; mi < 2; mi++)
                #pragma unroll
                for (int ni = 0; ni < 8; ni++)
                    mma_tf32(acc[mi][ni], afr[mi][0], afr[mi][1], afr[mi][2], afr[mi][3],
                             bfr[ni][0], bfr[ni][1]);
            // spread the next tile's copy issue between math groups
            if (ks == 0 && pre) issueA(it + 2);
            if (ks == 1 && pre) { issueB(it + 2); cp_commit(); }
        }
    }

    // ---- epilogue ----
    #pragma unroll
    for (int mi = 0; mi < 2; mi++) {
        #pragma unroll
        for (int ni = 0; ni < 8; ni++) {
            int row = m0 + wm * 32 + mi * 16 + gid;
            int col = n0 + wn * 64 + ni * 8 + tig * 2;
            float v0 = acc[mi][ni][0];
            float v1 = acc[mi][ni][1];
            float v2 = acc[mi][ni][2];
            float v3 = acc[mi][ni][3];
            if (bias) {
                float bb0 = bias[col], bb1 = bias[col + 1];
                v0 += bb0; v1 += bb1; v2 += bb0; v3 += bb1;
            }
            if (GELU) {
                v0 = 0.5f * v0 * (1.f + erff(v0 * 0.70710678118654752f));
                v1 = 0.5f * v1 * (1.f + erff(v1 * 0.70710678118654752f));
                v2 = 0.5f * v2 * (1.f + erff(v2 * 0.70710678118654752f));
                v3 = 0.5f * v3 * (1.f + erff(v3 * 0.70710678118654752f));
            }
            if (res) {
                const float2 r0 = *reinterpret_cast<const float2*>(res + (size_t)row * ldc + col);
                const float2 r1 = *reinterpret_cast<const float2*>(res + (size_t)(row + 8) * ldc + col);
                v0 += r0.x; v1 += r0.y; v2 += r1.x; v3 += r1.y;
            }
            *reinterpret_cast<float2*>(C + (size_t)row * ldc + col)       = make_float2(v0, v1);
            *reinterpret_cast<float2*>(C + (size_t)(row + 8) * ldc + col) = make_float2(v2, v3);
        }
    }
}

// ---------------- launch ---------------------------------------------------------
extern "C" void kernel_launch(void* const* d_in, const int* in_sizes, int n_in,
                              void* d_out, int out_size) {
    const float* x      = (const float*)d_in[0];
    const float* g1     = (const float*)d_in[1];
    const float* b1     = (const float*)d_in[2];
    const float* g2     = (const float*)d_in[3];
    const float* b2     = (const float*)d_in[4];
    const float* w_qkv  = (const float*)d_in[5];
    const float* w_proj = (const float*)d_in[6];
    const float* b_proj = (const float*)d_in[7];
    const float* w_fc1  = (const float*)d_in[8];
    const float* b_fc1  = (const float*)d_in[9];
    const float* w_fc2  = (const float*)d_in[10];
    const float* b_fc2  = (const float*)d_in[11];
    float* out = (float*)d_out;

    float *p_h, *p_qkv, *p_attn, *p_x2, *p_h2, *p_hid;
    cudaGetSymbolAddress((void**)&p_h,    g_h);
    cudaGetSymbolAddress((void**)&p_qkv,  g_qkv);
    cudaGetSymbolAddress((void**)&p_attn, g_attn);
    cudaGetSymbolAddress((void**)&p_x2,   g_x2);
    cudaGetSymbolAddress((void**)&p_h2,   g_h2);
    cudaGetSymbolAddress((void**)&p_hid,  g_hid);

    static bool attr_set = false;
    if (!attr_set) {
        cudaFuncSetAttribute(flash_kernel,
                             cudaFuncAttributeMaxDynamicSharedMemorySize, FLASH_SMEM);
        cudaFuncSetAttribute(gemm_cp<false>,
                             cudaFuncAttributeMaxDynamicSharedMemorySize, GEMM_SMEM);
        cudaFuncSetAttribute(gemm_cp<true>,
                             cudaFuncAttributeMaxDynamicSharedMemorySize, GEMM_SMEM);
        attr_set = true;
    }

    // 1) LN1
    ln_kernel<<<TOKENS, 256>>>(x, g1, b1, p_h);

    // 2) qkv = h @ w_qkv
    gemm_cp<false><<<dim3(3*EMBED/128, TOKENS/128), 256, GEMM_SMEM>>>(
        p_h, w_qkv, p_qkv, EMBED, EMBED, 3*EMBED, 3*EMBED, nullptr, nullptr);

    // 3-5) fused attention
    flash_kernel<<<dim3(SEQ/BQ, BHT), 256, FLASH_SMEM>>>(p_qkv, p_attn);

    // 6) x2 = attn @ w_proj + b_proj + x
    gemm_cp<false><<<dim3(EMBED/128, TOKENS/128), 256, GEMM_SMEM>>>(
        p_attn, w_proj, p_x2, EMBED, EMBED, EMBED, EMBED, b_proj, x);

    // 7) LN2
    ln_kernel<<<TOKENS, 256>>>(p_x2, g2, b2, p_h2);

    // 8) hid = gelu(h2 @ w_fc1 + b_fc1)
    gemm_cp<true><<<dim3(HIDDEN/128, TOKENS/128), 256, GEMM_SMEM>>>(
        p_h2, w_fc1, p_hid, EMBED, EMBED, HIDDEN, HIDDEN, b_fc1, nullptr);

    // 9) out = hid @ w_fc2 + b_fc2 + x2
    gemm_cp<false><<<dim3(EMBED/128, TOKENS/128), 256, GEMM_SMEM>>>(
        p_hid, w_fc2, out, HIDDEN, HIDDEN, EMBED, EMBED, b_fc2, p_x2);
}

// round 8
// speedup vs baseline: 4.4013x; 1.0121x over previous
#include <cuda_runtime.h>
#include <math.h>
#include <stdint.h>

#define EMBED   768
#define HEADS   12
#define HDIM    64
#define HIDDEN  3072
#define BATCHSZ 8
#define SEQ     1024
#define TOKENS  (BATCHSZ*SEQ)     // 8192
#define BHT     (BATCHSZ*HEADS)   // 96

// ---------------- scratch ----------------------------------------------------
__device__ float g_h   [(size_t)TOKENS*EMBED];
__device__ float g_qkv [(size_t)TOKENS*3*EMBED];
__device__ float g_attn[(size_t)TOKENS*EMBED];
__device__ float g_x2  [(size_t)TOKENS*EMBED];
__device__ float g_h2  [(size_t)TOKENS*EMBED];
__device__ float g_hid [(size_t)TOKENS*HIDDEN];

// ---------------- LayerNorm ---------------------------------------------------
__global__ void ln_kernel(const float* __restrict__ x,
                          const float* __restrict__ g,
                          const float* __restrict__ b,
                          float* __restrict__ out) {
    int row = blockIdx.x;
    const float* xr = x + (size_t)row * EMBED;
    float s = 0.f, s2 = 0.f;
    for (int i = threadIdx.x; i < EMBED; i += blockDim.x) {
        float v = xr[i]; s += v; s2 += v * v;
    }
    __shared__ float red[64];
    int wid = threadIdx.x >> 5, lid = threadIdx.x & 31;
    #pragma unroll
    for (int o = 16; o; o >>= 1) {
        s  += __shfl_down_sync(0xffffffffu, s,  o);
        s2 += __shfl_down_sync(0xffffffffu, s2, o);
    }
    if (lid == 0) { red[wid] = s; red[wid + 32] = s2; }
    __syncthreads();
    if (wid == 0) {
        int nw = blockDim.x >> 5;
        s  = (lid < nw) ? red[lid]      : 0.f;
        s2 = (lid < nw) ? red[lid + 32] : 0.f;
        #pragma unroll
        for (int o = 16; o; o >>= 1) {
            s  += __shfl_down_sync(0xffffffffu, s,  o);
            s2 += __shfl_down_sync(0xffffffffu, s2, o);
        }
        if (lid == 0) { red[0] = s; red[1] = s2; }
    }
    __syncthreads();
    float mu  = red[0] * (1.f / EMBED);
    float var = red[1] * (1.f / EMBED) - mu * mu;
    float rstd = rsqrtf(var + 1e-5f);
    float* o = out + (size_t)row * EMBED;
    for (int i = threadIdx.x; i < EMBED; i += blockDim.x)
        o[i] = (xr[i] - mu) * rstd * g[i] + b[i];
}

// ---------------- mma helper -----------------------------------------------------
__device__ __forceinline__ void mma_tf32(float c[4],
                                         uint32_t a0, uint32_t a1, uint32_t a2, uint32_t a3,
                                         uint32_t b0, uint32_t b1) {
    asm volatile(
        "mma.sync.aligned.m16n8k8.row.col.f32.tf32.tf32.f32 "
        "{%0,%1,%2,%3}, {%4,%5,%6,%7}, {%8,%9}, {%0,%1,%2,%3};"
        : "+f"(c[0]), "+f"(c[1]), "+f"(c[2]), "+f"(c[3])
        : "r"(a0), "r"(a1), "r"(a2), "r"(a3), "r"(b0), "r"(b1));
}

__device__ __forceinline__ void cpasync16(uint32_t s, const void* g) {
    asm volatile("cp.async.cg.shared.global [%0], [%1], 16;" :: "r"(s), "l"(g));
}
__device__ __forceinline__ void cp_commit() {
    asm volatile("cp.async.commit_group;");
}

// ---------------- fused flash attention (BKV=64, 2 CTAs/SM) -----------------------
// Per CTA: 128 Q rows of one (b,h). Q fragments in registers. KV tiles of 64 tokens,
// double-buffered via cp.async. smem ~106.5 KB -> 2 CTAs/SM (16 warps resident).
#define BQ  128
#define BKV 64
#define KD_ST 68
#define VD_ST 72
#define PS_ST 68                                      // BKV + 4
#define PS_FLOATS   (BQ * PS_ST)                      // 8704
#define KVS_FLOATS  (BKV * (KD_ST + VD_ST))           // 8960 per stage
#define FLASH_SMEM  ((PS_FLOATS + 2 * KVS_FLOATS) * 4)    // 106496 B

__global__ void __launch_bounds__(256, 2)
flash_kernel(const float* __restrict__ qkv, float* __restrict__ attn) {
    extern __shared__ float sm[];
    float* Ps  = sm;                                  // also Q staging initially
    float* KV0 = sm + PS_FLOATS;
    float* KV1 = KV0 + KVS_FLOATS;

    const int tid  = threadIdx.x;
    const int warp = tid >> 5, lane = tid & 31;
    const int gid  = lane >> 2, tig = lane & 3;
    const int bh = blockIdx.y;
    const int b  = bh / HEADS, h = bh % HEADS;
    const int q0 = blockIdx.x * BQ;
    const int wrow = warp * 16;
    float* Pw = Ps + warp * 16 * PS_ST;

    const float* qbase = qkv + ((size_t)b * SEQ) * 3 * EMBED + h * HDIM;
    const float* kbase = qbase + EMBED;
    const float* vbase = qbase + 2 * EMBED;

    // ---- stage Q (scaled) into Ps rows (PS_ST >= HDIM+4), lift fragments ----
    #pragma unroll
    for (int i = 0; i < 8; i++) {
        int s = tid + i * 256;
        int r = s >> 4, c = (s & 15) * 4;
        float4 v = *reinterpret_cast<const float4*>(qbase + (size_t)(q0 + r) * 3 * EMBED + c);
        *reinterpret_cast<float4*>(&Ps[r * PS_ST + c]) =
            make_float4(v.x * 0.125f, v.y * 0.125f, v.z * 0.125f, v.w * 0.125f);
    }
    __syncthreads();
    uint32_t qf[8][4];
    #pragma unroll
    for (int ks = 0; ks < 8; ks++) {
        const int k = ks * 8;
        qf[ks][0] = __float_as_uint(Ps[(wrow + gid)     * PS_ST + k + tig]);
        qf[ks][1] = __float_as_uint(Ps[(wrow + gid + 8) * PS_ST + k + tig]);
        qf[ks][2] = __float_as_uint(Ps[(wrow + gid)     * PS_ST + k + tig + 4]);
        qf[ks][3] = __float_as_uint(Ps[(wrow + gid + 8) * PS_ST + k + tig + 4]);
    }
    __syncthreads();   // Ps free for P use

    // ---- KV stage loader: 64 rows x 64 floats for K and V ----
    const uint32_t kv0s = (uint32_t)__cvta_generic_to_shared(KV0);
    const uint32_t kv1s = (uint32_t)__cvta_generic_to_shared(KV1);
    auto issue_kv = [&](int t) {
        const uint32_t base = (t & 1) ? kv1s : kv0s;
        const uint32_t vofs = BKV * KD_ST * 4;
        #pragma unroll
        for (int p = 0; p < 4; p++) {
            int c = tid + p * 256;
            int r = c >> 4, c16 = c & 15;
            size_t gro = (size_t)(t * BKV + r) * 3 * EMBED + c16 * 4;
            cpasync16(base + (r * KD_ST + c16 * 4) * 4,        kbase + gro);
            cpasync16(base + vofs + (r * VD_ST + c16 * 4) * 4, vbase + gro);
        }
        cp_commit();
    };

    float m0 = -1e30f, m1 = -1e30f, l0 = 0.f, l1 = 0.f;
    float oacc[8][4];
    #pragma unroll
    for (int ni = 0; ni < 8; ni++)
        #pragma unroll
        for (int q = 0; q < 4; q++) oacc[ni][q] = 0.f;

    issue_kv(0);

    for (int t = 0; t < SEQ / BKV; t++) {
        if (t + 1 < SEQ / BKV) {
            issue_kv(t + 1);
            asm volatile("cp.async.wait_group 1;");
        } else {
            asm volatile("cp.async.wait_group 0;");
        }
        __syncthreads();

        const float* Ks = (t & 1) ? KV1 : KV0;
        const float* Vs = Ks + BKV * KD_ST;

        // ---- S = Q @ K^T  (16 x 64 per warp) ----
        float sacc[8][4];
        #pragma unroll
        for (int ni = 0; ni < 8; ni++)
            #pragma unroll
            for (int q = 0; q < 4; q++) sacc[ni][q] = 0.f;

        #pragma unroll
        for (int ks = 0; ks < 8; ks++) {
            const int k = ks * 8;
            #pragma unroll
            for (int ni = 0; ni < 8; ni++) {
                uint32_t b0 = __float_as_uint(Ks[(ni * 8 + gid) * KD_ST + k + tig]);
                uint32_t b1 = __float_as_uint(Ks[(ni * 8 + gid) * KD_ST + k + tig + 4]);
                mma_tf32(sacc[ni], qf[ks][0], qf[ks][1], qf[ks][2], qf[ks][3], b0, b1);
            }
        }

        // ---- online softmax over 64 cols ----
        float rmax0 = -1e30f, rmax1 = -1e30f;
        #pragma unroll
        for (int ni = 0; ni < 8; ni++) {
            rmax0 = fmaxf(rmax0, fmaxf(sacc[ni][0], sacc[ni][1]));
            rmax1 = fmaxf(rmax1, fmaxf(sacc[ni][2], sacc[ni][3]));
        }
        #pragma unroll
        for (int o = 1; o <= 2; o <<= 1) {
            rmax0 = fmaxf(rmax0, __shfl_xor_sync(0xffffffffu, rmax0, o));
            rmax1 = fmaxf(rmax1, __shfl_xor_sync(0xffffffffu, rmax1, o));
        }
        float mn0 = fmaxf(m0, rmax0);
        float mn1 = fmaxf(m1, rmax1);
        float sf0 = __expf(m0 - mn0);
        float sf1 = __expf(m1 - mn1);

        float rs0 = 0.f, rs1 = 0.f;
        #pragma unroll
        for (int ni = 0; ni < 8; ni++) {
            float p0 = __expf(sacc[ni][0] - mn0);
            float p1 = __expf(sacc[ni][1] - mn0);
            float p2 = __expf(sacc[ni][2] - mn1);
            float p3 = __expf(sacc[ni][3] - mn1);
            rs0 += p0 + p1;
            rs1 += p2 + p3;
            int cc = ni * 8 + tig * 2;
            *reinterpret_cast<float2*>(&Pw[gid * PS_ST + cc])       = make_float2(p0, p1);
            *reinterpret_cast<float2*>(&Pw[(gid + 8) * PS_ST + cc]) = make_float2(p2, p3);
        }
        #pragma unroll
        for (int o = 1; o <= 2; o <<= 1) {
            rs0 += __shfl_xor_sync(0xffffffffu, rs0, o);
            rs1 += __shfl_xor_sync(0xffffffffu, rs1, o);
        }
        l0 = l0 * sf0 + rs0;
        l1 = l1 * sf1 + rs1;
        m0 = mn0;
        m1 = mn1;

        #pragma unroll
        for (int ni = 0; ni < 8; ni++) {
            oacc[ni][0] *= sf0; oacc[ni][1] *= sf0;
            oacc[ni][2] *= sf1; oacc[ni][3] *= sf1;
        }
        __syncwarp();

        // ---- O += P @ V  (K = 64) ----
        #pragma unroll
        for (int ks = 0; ks < 8; ks++) {
            const int k = ks * 8;
            uint32_t a0 = __float_as_uint(Pw[gid * PS_ST + k + tig]);
            uint32_t a1 = __float_as_uint(Pw[(gid + 8) * PS_ST + k + tig]);
            uint32_t a2 = __float_as_uint(Pw[gid * PS_ST + k + tig + 4]);
            uint32_t a3 = __float_as_uint(Pw[(gid + 8) * PS_ST + k + tig + 4]);
            #pragma unroll
            for (int ni = 0; ni < 8; ni++) {
                uint32_t b0 = __float_as_uint(Vs[(k + tig)     * VD_ST + ni * 8 + gid]);
                uint32_t b1 = __float_as_uint(Vs[(k + tig + 4) * VD_ST + ni * 8 + gid]);
                mma_tf32(oacc[ni], a0, a1, a2, a3, b0, b1);
            }
        }
        __syncthreads();   // all warps done with buffer t before refill (t+2)
    }

    float inv0 = 1.f / l0;
    float inv1 = 1.f / l1;
    const int tok0 = b * SEQ + q0 + wrow;
    #pragma unroll
    for (int ni = 0; ni < 8; ni++) {
        int col = h * HDIM + ni * 8 + tig * 2;
        *reinterpret_cast<float2*>(attn + (size_t)(tok0 + gid) * EMBED + col) =
            make_float2(oacc[ni][0] * inv0, oacc[ni][1] * inv0);
        *reinterpret_cast<float2*>(attn + (size_t)(tok0 + gid + 8) * EMBED + col) =
            make_float2(oacc[ni][2] * inv1, oacc[ni][3] * inv1);
    }
}

// ---------------- cp.async pipelined tensor-core GEMM (NN, BK=32) -----------------
#define GSTAGES 3
#define GBK  32
#define G_AS 36
#define G_BS 136
#define G_ASZ (128 * G_AS)
#define G_BSZ (GBK * G_BS)
#define GEMM_SMEM (GSTAGES * (G_ASZ + G_BSZ) * 4)   // 107520 B

template<bool GELU>
__global__ void __launch_bounds__(256, 2)
gemm_cp(const float* __restrict__ A, const float* __restrict__ B,
        float* __restrict__ C,
        int K, int lda, int ldb, int ldc,
        const float* __restrict__ bias,
        const float* __restrict__ res) {
    extern __shared__ float smp[];
    float* AsB = smp;
    float* BsB = smp + GSTAGES * G_ASZ;

    const int tid = threadIdx.x;
    const int warp = tid >> 5, lane = tid & 31;
    const int gid = lane >> 2, tig = lane & 3;
    const int wm = warp >> 1, wn = warp & 1;

    const int m0 = blockIdx.y * 128;
    const int n0 = blockIdx.x * 128;

    const uint32_t asb = (uint32_t)__cvta_generic_to_shared(AsB);
    const uint32_t bsb = (uint32_t)__cvta_generic_to_shared(BsB);

    const int niter = K / GBK;

    auto issueA = [&](int it) {
        const int stage = it % GSTAGES;
        const uint32_t ao = asb + stage * (G_ASZ * 4);
        const int k0 = it * GBK;
        #pragma unroll
        for (int p = 0; p < 4; p++) {
            int c = tid + p * 256;
            int row = c >> 3, kc = (c & 7) * 4;
            cpasync16(ao + (row * G_AS + kc) * 4,
                      A + (size_t)(m0 + row) * lda + k0 + kc);
        }
    };
    auto issueB = [&](int it) {
        const int stage = it % GSTAGES;
        const uint32_t bo = bsb + stage * (G_BSZ * 4);
        const int k0 = it * GBK;
        #pragma unroll
        for (int p = 0; p < 4; p++) {
            int c = tid + p * 256;
            int k = c >> 5, n4 = (c & 31) * 4;
            cpasync16(bo + (k * G_BS + n4) * 4,
                      B + (size_t)(k0 + k) * ldb + n0 + n4);
        }
    };

    float acc[2][8][4];
    #pragma unroll
    for (int mi = 0; mi < 2; mi++)
        #pragma unroll
        for (int ni = 0; ni < 8; ni++)
            #pragma unroll
            for (int q = 0; q < 4; q++) acc[mi][ni][q] = 0.f;

    issueA(0); issueB(0); cp_commit();
    issueA(1); issueB(1); cp_commit();

    for (int it = 0; it < niter; ++it) {
        if (it + 1 < niter) asm volatile("cp.async.wait_group 1;");
        else                asm volatile("cp.async.wait_group 0;");
        __syncthreads();

        const int stage = it % GSTAGES;
        const float* As = AsB + stage * G_ASZ;
        const float* Bs = BsB + stage * G_BSZ;
        const bool pre = (it + 2 < niter);

        #pragma unroll
        for (int ks = 0; ks < GBK / 8; ks++) {
            const int k = ks * 8;
            uint32_t afr[2][4];
            #pragma unroll
            for (int mi = 0; mi < 2; mi++) {
                int rbse = wm * 32 + mi * 16;
                afr[mi][0] = __float_as_uint(As[(rbse + gid)     * G_AS + k + tig]);
                afr[mi][1] = __float_as_uint(As[(rbse + gid + 8) * G_AS + k + tig]);
                afr[mi][2] = __float_as_uint(As[(rbse + gid)     * G_AS + k + tig + 4]);
                afr[mi][3] = __float_as_uint(As[(rbse + gid + 8) * G_AS + k + tig + 4]);
            }
            uint32_t bfr[8][2];
            #pragma unroll
            for (int ni = 0; ni < 8; ni++) {
                int col = wn * 64 + ni * 8 + gid;
                bfr[ni][0] = __float_as_uint(Bs[(k + tig)     * G_BS + col]);
                bfr[ni][1] = __float_as_uint(Bs[(k + tig + 4) * G_BS + col]);
            }
            #pragma unroll
            for (int mi = 0; mi < 2; mi++)
                #pragma unroll
                for (int ni = 0; ni < 8; ni++)
                    mma_tf32(acc[mi][ni], afr[mi][0], afr[mi][1], afr[mi][2], afr[mi][3],
                             bfr[ni][0], bfr[ni][1]);
            if (ks == 0 && pre) issueA(it + 2);
            if (ks == 1 && pre) { issueB(it + 2); cp_commit(); }
        }
    }

    // ---- epilogue ----
    #pragma unroll
    for (int mi = 0; mi < 2; mi++) {
        #pragma unroll
        for (int ni = 0; ni < 8; ni++) {
            int row = m0 + wm * 32 + mi * 16 + gid;
            int col = n0 + wn * 64 + ni * 8 + tig * 2;
            float v0 = acc[mi][ni][0];
            float v1 = acc[mi][ni][1];
            float v2 = acc[mi][ni][2];
            float v3 = acc[mi][ni][3];
            if (bias) {
                float bb0 = bias[col], bb1 = bias[col + 1];
                v0 += bb0; v1 += bb1; v2 += bb0; v3 += bb1;
            }
            if (GELU) {
                v0 = 0.5f * v0 * (1.f + erff(v0 * 0.70710678118654752f));
                v1 = 0.5f * v1 * (1.f + erff(v1 * 0.70710678118654752f));
                v2 = 0.5f * v2 * (1.f + erff(v2 * 0.70710678118654752f));
                v3 = 0.5f * v3 * (1.f + erff(v3 * 0.70710678118654752f));
            }
            if (res) {
                const float2 r0 = *reinterpret_cast<const float2*>(res + (size_t)row * ldc + col);
                const float2 r1 = *reinterpret_cast<const float2*>(res + (size_t)(row + 8) * ldc + col);
                v0 += r0.x; v1 += r0.y; v2 += r1.x; v3 += r1.y;
            }
            *reinterpret_cast<float2*>(C + (size_t)row * ldc + col)       = make_float2(v0, v1);
            *reinterpret_cast<float2*>(C + (size_t)(row + 8) * ldc + col) = make_float2(v2, v3);
        }
    }
}

// ---------------- launch ---------------------------------------------------------
extern "C" void kernel_launch(void* const* d_in, const int* in_sizes, int n_in,
                              void* d_out, int out_size) {
    const float* x      = (const float*)d_in[0];
    const float* g1     = (const float*)d_in[1];
    const float* b1     = (const float*)d_in[2];
    const float* g2     = (const float*)d_in[3];
    const float* b2     = (const float*)d_in[4];
    const float* w_qkv  = (const float*)d_in[5];
    const float* w_proj = (const float*)d_in[6];
    const float* b_proj = (const float*)d_in[7];
    const float* w_fc1  = (const float*)d_in[8];
    const float* b_fc1  = (const float*)d_in[9];
    const float* w_fc2  = (const float*)d_in[10];
    const float* b_fc2  = (const float*)d_in[11];
    float* out = (float*)d_out;

    float *p_h, *p_qkv, *p_attn, *p_x2, *p_h2, *p_hid;
    cudaGetSymbolAddress((void**)&p_h,    g_h);
    cudaGetSymbolAddress((void**)&p_qkv,  g_qkv);
    cudaGetSymbolAddress((void**)&p_attn, g_attn);
    cudaGetSymbolAddress((void**)&p_x2,   g_x2);
    cudaGetSymbolAddress((void**)&p_h2,   g_h2);
    cudaGetSymbolAddress((void**)&p_hid,  g_hid);

    static bool attr_set = false;
    if (!attr_set) {
        cudaFuncSetAttribute(flash_kernel,
                             cudaFuncAttributeMaxDynamicSharedMemorySize, FLASH_SMEM);
        cudaFuncSetAttribute(gemm_cp<false>,
                             cudaFuncAttributeMaxDynamicSharedMemorySize, GEMM_SMEM);
        cudaFuncSetAttribute(gemm_cp<true>,
                             cudaFuncAttributeMaxDynamicSharedMemorySize, GEMM_SMEM);
        attr_set = true;
    }

    // 1) LN1
    ln_kernel<<<TOKENS, 256>>>(x, g1, b1, p_h);

    // 2) qkv = h @ w_qkv
    gemm_cp<false><<<dim3(3*EMBED/128, TOKENS/128), 256, GEMM_SMEM>>>(
        p_h, w_qkv, p_qkv, EMBED, EMBED, 3*EMBED, 3*EMBED, nullptr, nullptr);

    // 3-5) fused attention
    flash_kernel<<<dim3(SEQ/BQ, BHT), 256, FLASH_SMEM>>>(p_qkv, p_attn);

    // 6) x2 = attn @ w_proj + b_proj + x
    gemm_cp<false><<<dim3(EMBED/128, TOKENS/128), 256, GEMM_SMEM>>>(
        p_attn, w_proj, p_x2, EMBED, EMBED, EMBED, EMBED, b_proj, x);

    // 7) LN2
    ln_kernel<<<TOKENS, 256>>>(p_x2, g2, b2, p_h2);

    // 8) hid = gelu(h2 @ w_fc1 + b_fc1)
    gemm_cp<true><<<dim3(HIDDEN/128, TOKENS/128), 256, GEMM_SMEM>>>(
        p_h2, w_fc1, p_hid, EMBED, EMBED, HIDDEN, HIDDEN, b_fc1, nullptr);

    // 9) out = hid @ w_fc2 + b_fc2 + x2
    gemm_cp<false><<<dim3(EMBED/128, TOKENS/128), 256, GEMM_SMEM>>>(
        p_hid, w_fc2, out, HIDDEN, HIDDEN, EMBED, EMBED, b_fc2, p_x2);
}